// round 1
// baseline (speedup 1.0000x reference)
#include <cuda_runtime.h>
#include <cstdint>
#include <math.h>

// Problem constants
#define BB 32
#define CC 128
#define HH 16
#define WW 16
#define VV 8192
#define NUMEL (BB*CC*HH*WW)   // 1048576

// ---------------- device scratch (no allocs allowed) ----------------
__device__ float g_frest[NUMEL];
__device__ float g_fhat[NUMEL];
__device__ float g_restNC[VV*CC];          // max N = 8192 rows of 128
__device__ float g_esq[VV];
__device__ unsigned long long g_packed[VV]; // (ordered_score<<32)|idx
__device__ float g_h[NUMEL];
__device__ float g_h2[NUMEL];
__device__ float g_loss;

// ---------------- init: f_rest = f, f_hat = 0, loss = 0 ----------------
__global__ void k_init(const float* __restrict__ f) {
    int i = blockIdx.x * 256 + threadIdx.x;
    g_frest[i] = f[i];
    g_fhat[i] = 0.f;
    if (i == 0) g_loss = 0.f;
}

// ---------------- e_sq: one warp per code row ----------------
__global__ void k_esq(const float* __restrict__ emb) {
    int gw = (blockIdx.x * blockDim.x + threadIdx.x) >> 5;
    int lane = threadIdx.x & 31;
    float4 v = *(const float4*)(emb + (size_t)gw * CC + lane * 4);
    float s = v.x*v.x + v.y*v.y + v.z*v.z + v.w*v.w;
    #pragma unroll
    for (int o = 16; o; o >>= 1) s += __shfl_xor_sync(0xffffffffu, s, o);
    if (lane == 0) g_esq[gw] = s;
}

// ---------------- pool: rest_NC[n][c] = blockmean(f_rest), reset packed ----------------
__global__ void k_pool(int pn, int s, int N) {
    int n = blockIdx.x;
    int c = threadIdx.x;
    int b = n / (pn * pn);
    int rem = n - b * pn * pn;
    int py = rem / pn, px = rem - py * pn;
    const float* base = g_frest + ((size_t)(b * CC + c)) * 256;
    float sum = 0.f;
    for (int dy = 0; dy < s; dy++)
        for (int dx = 0; dx < s; dx++)
            sum += base[(py * s + dy) * 16 + (px * s + dx)];
    g_restNC[(size_t)n * CC + c] = sum * (1.f / (float)(s * s));
    if (c == 0) g_packed[n] = ~0ull;
}

// ---------------- argmin: 64 rows x (codesPerBlock) codes, 2x4 thread tile ----------------
// smem = 32KB rows + 16KB codesT = exactly 48KB static
__global__ void k_argmin(const float* __restrict__ emb, int N, int codesPerBlock) {
    __shared__ float rows[64][128];
    __shared__ float codesT[128][32];
    int tid = threadIdx.x;
    int n0 = blockIdx.x * 64;
    int v0 = blockIdx.y * codesPerBlock;

    // load 64 rows (zero-pad beyond N)
    for (int i = tid; i < 64 * 32; i += 256) {
        int r = i >> 5, q = (i & 31) << 2;
        float4 v = make_float4(0.f, 0.f, 0.f, 0.f);
        int n = n0 + r;
        if (n < N) v = *(const float4*)(g_restNC + (size_t)n * CC + q);
        *(float4*)(&rows[r][q]) = v;
    }

    int cg = tid & 7;    // codes cg*4 .. cg*4+3
    int rg = tid >> 3;   // rows rg, rg+32
    unsigned long long best0 = ~0ull, best1 = ~0ull;

    for (int c0 = v0; c0 < v0 + codesPerBlock; c0 += 32) {
        __syncthreads();
        // stage 32 codes transposed: codesT[k][code]
        for (int i = tid; i < 32 * 32; i += 256) {
            int r = i >> 5, q = (i & 31) << 2;
            float4 v = *(const float4*)(emb + (size_t)(c0 + r) * CC + q);
            codesT[q + 0][r] = v.x;
            codesT[q + 1][r] = v.y;
            codesT[q + 2][r] = v.z;
            codesT[q + 3][r] = v.w;
        }
        __syncthreads();

        float acc00 = 0.f, acc01 = 0.f, acc02 = 0.f, acc03 = 0.f;
        float acc10 = 0.f, acc11 = 0.f, acc12 = 0.f, acc13 = 0.f;
        #pragma unroll
        for (int k4 = 0; k4 < 32; k4++) {
            float4 r0 = *(const float4*)(&rows[rg][k4 * 4]);
            float4 r1 = *(const float4*)(&rows[rg + 32][k4 * 4]);
            #pragma unroll
            for (int kk = 0; kk < 4; kk++) {
                float4 cv = *(const float4*)(&codesT[k4 * 4 + kk][cg * 4]);
                float a = (kk == 0) ? r0.x : (kk == 1) ? r0.y : (kk == 2) ? r0.z : r0.w;
                float b = (kk == 0) ? r1.x : (kk == 1) ? r1.y : (kk == 2) ? r1.z : r1.w;
                acc00 += a * cv.x; acc01 += a * cv.y; acc02 += a * cv.z; acc03 += a * cv.w;
                acc10 += b * cv.x; acc11 += b * cv.y; acc12 += b * cv.z; acc13 += b * cv.w;
            }
        }

        float d0[4] = {acc00, acc01, acc02, acc03};
        float d1[4] = {acc10, acc11, acc12, acc13};
        #pragma unroll
        for (int j = 0; j < 4; j++) {
            int c = c0 + cg * 4 + j;
            float es = g_esq[c];
            float s0 = fmaf(-2.f, d0[j], es);
            float s1 = fmaf(-2.f, d1[j], es);
            unsigned u0 = __float_as_uint(s0);
            u0 = (u0 & 0x80000000u) ? ~u0 : (u0 | 0x80000000u);
            unsigned u1 = __float_as_uint(s1);
            u1 = (u1 & 0x80000000u) ? ~u1 : (u1 | 0x80000000u);
            unsigned long long p0 = ((unsigned long long)u0 << 32) | (unsigned)c;
            unsigned long long p1 = ((unsigned long long)u1 << 32) | (unsigned)c;
            if (p0 < best0) best0 = p0;
            if (p1 < best1) best1 = p1;
        }
    }

    // reduce across the 8 code-groups (consecutive lanes)
    #pragma unroll
    for (int s = 4; s; s >>= 1) {
        unsigned long long o0 = __shfl_xor_sync(0xffffffffu, best0, s, 8);
        if (o0 < best0) best0 = o0;
        unsigned long long o1 = __shfl_xor_sync(0xffffffffu, best1, s, 8);
        if (o1 < best1) best1 = o1;
    }
    if (cg == 0) {
        if (n0 + rg < N)      atomicMin(&g_packed[n0 + rg], best0);
        if (n0 + rg + 32 < N) atomicMin(&g_packed[n0 + rg + 32], best1);
    }
}

// ---------------- bicubic weights (jax keys a=-0.5, half-pixel, row-normalized) ----------------
template <int PN>
__device__ __forceinline__ void cubic_weights(int j, float* w) {
    float sf = (j + 0.5f) * ((float)PN / 16.f) - 0.5f;
    float tot = 0.f;
    #pragma unroll
    for (int i = 0; i < PN; i++) {
        float x = fabsf(sf - (float)i);
        float v = 0.f;
        if (x <= 1.f)      v = ((1.5f * x - 2.5f) * x) * x + 1.f;
        else if (x < 2.f)  v = ((-0.5f * x + 2.5f) * x - 4.f) * x + 2.f;
        w[i] = v;
        tot += v;
    }
    float r = 1.f / tot;
    #pragma unroll
    for (int i = 0; i < PN; i++) w[i] *= r;
}

// ---------------- gather + bicubic upsample to 16x16 (one block per b) ----------------
template <int PN>
__global__ void k_upsample(const float* __restrict__ emb) {
    const int NP = PN * PN;
    __shared__ float g[64][128];      // NP <= 64
    __shared__ float wtab[16][8];     // same mapping for x and y
    int b = blockIdx.x;
    for (int i = threadIdx.x; i < NP * CC; i += 256) {
        int p = i >> 7, c = i & 127;
        unsigned idx = (unsigned)(g_packed[b * NP + p] & 0xffffffffu);
        g[p][c] = emb[(size_t)idx * CC + c];
    }
    if (threadIdx.x < 16) cubic_weights<PN>(threadIdx.x, &wtab[threadIdx.x][0]);
    __syncthreads();

    for (int o = threadIdx.x; o < 16 * 16 * CC; o += 256) {
        int c = o & 127;
        int sp = o >> 7;
        int x = sp & 15, y = sp >> 4;
        float acc = 0.f;
        #pragma unroll
        for (int iy = 0; iy < PN; iy++) {
            float ra = 0.f;
            #pragma unroll
            for (int ix = 0; ix < PN; ix++)
                ra += wtab[x][ix] * g[iy * PN + ix][c];
            acc += wtab[y][iy] * ra;
        }
        g_h[((size_t)(b * CC + c)) * 256 + y * 16 + x] = acc;
    }
}

// ---------------- last stage: direct gather (pn = 16) ----------------
__global__ void k_gather16(const float* __restrict__ emb) {
    int n = blockIdx.x;
    int c = threadIdx.x;
    unsigned idx = (unsigned)(g_packed[n] & 0xffffffffu);
    int b = n >> 8, y = (n >> 4) & 15, x = n & 15;
    g_h[((size_t)(b * CC + c)) * 256 + y * 16 + x] = emb[(size_t)idx * CC + c];
}

// ---------------- Phi: out = 0.5*(h + conv3x3(h) + bias) ----------------
// grid (16 cout-tiles, 32 batch), 256 threads; 8 couts per block
__global__ void k_conv(const float* __restrict__ w, const float* __restrict__ bias) {
    __shared__ float sin_[18 * 18];
    __shared__ float sw[72];
    int ct = blockIdx.x;
    int b = blockIdx.y;
    int tid = threadIdx.x;
    int sg = tid >> 2;          // 0..63 spatial groups
    int cp = tid & 3;           // cout pair selector
    int y = sg >> 2;
    int x0 = (sg & 3) << 2;
    float acc[2][4] = {{0.f, 0.f, 0.f, 0.f}, {0.f, 0.f, 0.f, 0.f}};
    const float* hin = g_h + (size_t)b * CC * 256;

    for (int cin = 0; cin < CC; cin++) {
        for (int i = tid; i < 324; i += 256) {
            int iy = i / 18 - 1, ix = i % 18 - 1;
            float v = 0.f;
            if (iy >= 0 && iy < 16 && ix >= 0 && ix < 16)
                v = hin[cin * 256 + iy * 16 + ix];
            sin_[i] = v;
        }
        if (tid < 72) {
            int co = tid / 9, k = tid % 9;
            sw[tid] = w[((size_t)(ct * 8 + co) * CC + cin) * 9 + k];
        }
        __syncthreads();

        float iv[3][6];
        #pragma unroll
        for (int r = 0; r < 3; r++)
            #pragma unroll
            for (int ccx = 0; ccx < 6; ccx++)
                iv[r][ccx] = sin_[(y + r) * 18 + (x0 + ccx)];

        #pragma unroll
        for (int co = 0; co < 2; co++) {
            int cidx = cp * 2 + co;
            #pragma unroll
            for (int ky = 0; ky < 3; ky++)
                #pragma unroll
                for (int kx = 0; kx < 3; kx++) {
                    float wv = sw[cidx * 9 + ky * 3 + kx];
                    #pragma unroll
                    for (int xi = 0; xi < 4; xi++)
                        acc[co][xi] += iv[ky][xi + kx] * wv;
                }
        }
        __syncthreads();
    }

    #pragma unroll
    for (int co = 0; co < 2; co++) {
        int coid = ct * 8 + cp * 2 + co;
        float bv = bias[coid];
        #pragma unroll
        for (int xi = 0; xi < 4; xi++) {
            size_t oidx = ((size_t)(b * CC + coid)) * 256 + y * 16 + x0 + xi;
            g_h2[oidx] = 0.5f * (g_h[oidx] + acc[co][xi] + bv);
        }
    }
}

// ---------------- residual update + partial SSE + (last) straight-through out ----------------
__global__ void k_update(const float* __restrict__ f, float* __restrict__ dout, int is_last) {
    int i = blockIdx.x * 256 + threadIdx.x;
    float h2 = g_h2[i];
    float fh = g_fhat[i] + h2;
    g_fhat[i] = fh;
    g_frest[i] = g_frest[i] - h2;
    float fv = f[i];
    float d = fh - fv;
    if (is_last) dout[i] = d + fv;   // mirrors (f_hat - f) + f
    float s = d * d;
    #pragma unroll
    for (int o = 16; o; o >>= 1) s += __shfl_xor_sync(0xffffffffu, s, o);
    __shared__ float ws[8];
    int lane = threadIdx.x & 31, wp = threadIdx.x >> 5;
    if (lane == 0) ws[wp] = s;
    __syncthreads();
    if (threadIdx.x == 0) {
        float t = 0.f;
        #pragma unroll
        for (int k = 0; k < 8; k++) t += ws[k];
        atomicAdd(&g_loss, t);
    }
}

__global__ void k_final(float* dout, int out_size) {
    // loss = (1/SN) * sum_si (BETA+1)*SSE_si/numel
    dout[out_size - 1] = g_loss * (1.25f / (5.f * (float)NUMEL));
}

// ---------------- host ----------------
extern "C" void kernel_launch(void* const* d_in, const int* in_sizes, int n_in,
                              void* d_out, int out_size) {
    const float* f     = (const float*)d_in[0];
    const float* emb   = (const float*)d_in[1];
    const float* phi_w = (const float*)d_in[2];
    const float* phi_b = (const float*)d_in[3];
    float* out = (float*)d_out;

    // Replicate np.linspace(1/12, 11/12, 4) + argmin(|ticks - si/4|) in double.
    double start = 1.0 / 12.0;
    double stop = 1.0 - 1.0 / 12.0;
    double step = (stop - start) / 3.0;
    double ticks[4];
    ticks[0] = 0.0 * step + start;
    ticks[1] = 1.0 * step + start;
    ticks[2] = 2.0 * step + start;
    ticks[3] = stop;  // linspace pins the endpoint
    int kphi[5];
    for (int si = 0; si < 5; si++) {
        double t = (double)si / 4.0;
        int bi = 0;
        double bd = fabs(ticks[0] - t);
        for (int k = 1; k < 4; k++) {
            double d = fabs(ticks[k] - t);
            if (d < bd) { bd = d; bi = k; }
        }
        kphi[si] = bi;
    }

    const int pns[5]    = {1, 2, 4, 8, 16};
    const int vsplit[5] = {256, 128, 64, 16, 4};

    k_esq<<<1024, 256>>>(emb);
    k_init<<<NUMEL / 256, 256>>>(f);

    for (int si = 0; si < 5; si++) {
        int pn = pns[si];
        int s = 16 / pn;
        int N = BB * pn * pn;

        k_pool<<<N, 128>>>(pn, s, N);

        int rb = (N + 63) / 64;
        dim3 g(rb, vsplit[si]);
        k_argmin<<<g, 256>>>(emb, N, VV / vsplit[si]);

        if (si < 4) {
            switch (pn) {
                case 1: k_upsample<1><<<32, 256>>>(emb); break;
                case 2: k_upsample<2><<<32, 256>>>(emb); break;
                case 4: k_upsample<4><<<32, 256>>>(emb); break;
                case 8: k_upsample<8><<<32, 256>>>(emb); break;
            }
        } else {
            k_gather16<<<VV, 128>>>(emb);
        }

        const float* w  = phi_w + (size_t)kphi[si] * CC * CC * 9;
        const float* bb = phi_b + kphi[si] * CC;
        k_conv<<<dim3(16, 32), 256>>>(w, bb);

        k_update<<<NUMEL / 256, 256>>>(f, out, si == 4 ? 1 : 0);
    }

    k_final<<<1, 1>>>(out, out_size);
}

// round 2
// speedup vs baseline: 2.0617x; 2.0617x over previous
#include <cuda_runtime.h>
#include <cstdint>
#include <math.h>

// Problem constants
#define BB 32
#define CC 128
#define HH 16
#define WW 16
#define VV 8192
#define NUMEL (BB*CC*HH*WW)   // 1048576

// ---------------- device scratch (no allocs allowed) ----------------
__device__ float g_frest[NUMEL];
__device__ float g_fhat[NUMEL];
__device__ float g_restNC[VV*CC];          // max N = 8192 rows of 128
__device__ float g_esq[VV];
__device__ unsigned long long g_packed[VV]; // (ordered_score<<32)|idx
__device__ float g_h[NUMEL];
__device__ float g_h2[NUMEL];
__device__ float g_loss;

// ---------------- init: f_rest = f, f_hat = 0, loss = 0 ----------------
__global__ void k_init(const float* __restrict__ f) {
    int i = blockIdx.x * 256 + threadIdx.x;
    g_frest[i] = f[i];
    g_fhat[i] = 0.f;
    if (i == 0) g_loss = 0.f;
}

// ---------------- e_sq: one warp per code row ----------------
__global__ void k_esq(const float* __restrict__ emb) {
    int gw = (blockIdx.x * blockDim.x + threadIdx.x) >> 5;
    int lane = threadIdx.x & 31;
    float4 v = *(const float4*)(emb + (size_t)gw * CC + lane * 4);
    float s = v.x*v.x + v.y*v.y + v.z*v.z + v.w*v.w;
    #pragma unroll
    for (int o = 16; o; o >>= 1) s += __shfl_xor_sync(0xffffffffu, s, o);
    if (lane == 0) g_esq[gw] = s;
}

// ---------------- pool: rest_NC[n][c] = blockmean(f_rest), reset packed ----------------
__global__ void k_pool(int pn, int s, int N) {
    int n = blockIdx.x;
    int c = threadIdx.x;
    int b = n / (pn * pn);
    int rem = n - b * pn * pn;
    int py = rem / pn, px = rem - py * pn;
    const float* base = g_frest + ((size_t)(b * CC + c)) * 256;
    float sum = 0.f;
    for (int dy = 0; dy < s; dy++)
        for (int dx = 0; dx < s; dx++)
            sum += base[(py * s + dy) * 16 + (px * s + dx)];
    g_restNC[(size_t)n * CC + c] = sum * (1.f / (float)(s * s));
    if (c == 0) g_packed[n] = ~0ull;
}

// ---------------- argmin v2: SGEMM-style 128x128 tile, 8x8 per thread ----------------
// A = rest rows [N,128], B = codes [V,128]; score = esq[c] - 2*dot
__global__ __launch_bounds__(256, 2)
void k_argmin2(const float* __restrict__ emb, int N, int codesPerBlock) {
    __shared__ float As[16][136];   // [k][row], padded
    __shared__ float Bs[16][136];   // [k][code], padded
    int tid = threadIdx.x;
    int tx = tid & 15, ty = tid >> 4;
    int n0 = blockIdx.x * 128;
    int v0 = blockIdx.y * codesPerBlock;
    int nTiles = codesPerBlock >> 7;

    unsigned long long best[8];
    #pragma unroll
    for (int i = 0; i < 8; i++) best[i] = ~0ull;

    for (int ct = 0; ct < nTiles; ct++) {
        int c0 = v0 + (ct << 7);
        float acc[8][8];
        #pragma unroll
        for (int i = 0; i < 8; i++)
            #pragma unroll
            for (int j = 0; j < 8; j++) acc[i][j] = 0.f;

        for (int kc = 0; kc < 8; kc++) {
            int k0 = kc << 4;
            __syncthreads();
            // stage A chunk: 128 rows x 16 k  (512 float4, 2 per thread)
            #pragma unroll
            for (int h = 0; h < 2; h++) {
                int id = tid + h * 256;
                int row = id >> 2, q = id & 3;
                float4 v = make_float4(0.f, 0.f, 0.f, 0.f);
                int n = n0 + row;
                if (n < N) v = *(const float4*)(g_restNC + (size_t)n * CC + k0 + q * 4);
                As[q*4+0][row] = v.x; As[q*4+1][row] = v.y;
                As[q*4+2][row] = v.z; As[q*4+3][row] = v.w;
                float4 w = *(const float4*)(emb + (size_t)(c0 + row) * CC + k0 + q * 4);
                Bs[q*4+0][row] = w.x; Bs[q*4+1][row] = w.y;
                Bs[q*4+2][row] = w.z; Bs[q*4+3][row] = w.w;
            }
            __syncthreads();

            #pragma unroll
            for (int k = 0; k < 16; k++) {
                float4 a0 = *(const float4*)(&As[k][ty * 8]);
                float4 a1 = *(const float4*)(&As[k][ty * 8 + 4]);
                float4 b0 = *(const float4*)(&Bs[k][tx * 8]);
                float4 b1 = *(const float4*)(&Bs[k][tx * 8 + 4]);
                float a[8] = {a0.x,a0.y,a0.z,a0.w,a1.x,a1.y,a1.z,a1.w};
                float b[8] = {b0.x,b0.y,b0.z,b0.w,b1.x,b1.y,b1.z,b1.w};
                #pragma unroll
                for (int i = 0; i < 8; i++)
                    #pragma unroll
                    for (int j = 0; j < 8; j++)
                        acc[i][j] += a[i] * b[j];
            }
        }

        // finalize this code tile
        #pragma unroll
        for (int j = 0; j < 8; j++) {
            int c = c0 + tx * 8 + j;
            float es = g_esq[c];
            #pragma unroll
            for (int i = 0; i < 8; i++) {
                float s = fmaf(-2.f, acc[i][j], es);
                unsigned u = __float_as_uint(s);
                u = (u & 0x80000000u) ? ~u : (u | 0x80000000u);
                unsigned long long p = ((unsigned long long)u << 32) | (unsigned)c;
                if (p < best[i]) best[i] = p;
            }
        }
    }

    // reduce across the 16 tx lanes (same rows)
    #pragma unroll
    for (int o = 8; o; o >>= 1) {
        #pragma unroll
        for (int i = 0; i < 8; i++) {
            unsigned long long v = __shfl_xor_sync(0xffffffffu, best[i], o, 16);
            if (v < best[i]) best[i] = v;
        }
    }
    if (tx == 0) {
        #pragma unroll
        for (int i = 0; i < 8; i++) {
            int n = n0 + ty * 8 + i;
            if (n < N) atomicMin(&g_packed[n], best[i]);
        }
    }
}

// ---------------- bicubic weights (jax keys a=-0.5, half-pixel, row-normalized) ----------------
template <int PN>
__device__ __forceinline__ void cubic_weights(int j, float* w) {
    float sf = (j + 0.5f) * ((float)PN / 16.f) - 0.5f;
    float tot = 0.f;
    #pragma unroll
    for (int i = 0; i < PN; i++) {
        float x = fabsf(sf - (float)i);
        float v = 0.f;
        if (x <= 1.f)      v = ((1.5f * x - 2.5f) * x) * x + 1.f;
        else if (x < 2.f)  v = ((-0.5f * x + 2.5f) * x - 4.f) * x + 2.f;
        w[i] = v;
        tot += v;
    }
    float r = 1.f / tot;
    #pragma unroll
    for (int i = 0; i < PN; i++) w[i] *= r;
}

// ---------------- gather + bicubic upsample to 16x16 (one block per b) ----------------
template <int PN>
__global__ void k_upsample(const float* __restrict__ emb) {
    const int NP = PN * PN;
    __shared__ float g[64][128];      // NP <= 64
    __shared__ float wtab[16][8];
    int b = blockIdx.x;
    for (int i = threadIdx.x; i < NP * CC; i += 256) {
        int p = i >> 7, c = i & 127;
        unsigned idx = (unsigned)(g_packed[b * NP + p] & 0xffffffffu);
        g[p][c] = emb[(size_t)idx * CC + c];
    }
    if (threadIdx.x < 16) cubic_weights<PN>(threadIdx.x, &wtab[threadIdx.x][0]);
    __syncthreads();

    for (int o = threadIdx.x; o < 16 * 16 * CC; o += 256) {
        int c = o & 127;
        int sp = o >> 7;
        int x = sp & 15, y = sp >> 4;
        float acc = 0.f;
        #pragma unroll
        for (int iy = 0; iy < PN; iy++) {
            float ra = 0.f;
            #pragma unroll
            for (int ix = 0; ix < PN; ix++)
                ra += wtab[x][ix] * g[iy * PN + ix][c];
            acc += wtab[y][iy] * ra;
        }
        g_h[((size_t)(b * CC + c)) * 256 + y * 16 + x] = acc;
    }
}

// ---------------- last stage: direct gather (pn = 16) ----------------
__global__ void k_gather16(const float* __restrict__ emb) {
    int n = blockIdx.x;
    int c = threadIdx.x;
    unsigned idx = (unsigned)(g_packed[n] & 0xffffffffu);
    int b = n >> 8, y = (n >> 4) & 15, x = n & 15;
    g_h[((size_t)(b * CC + c)) * 256 + y * 16 + x] = emb[(size_t)idx * CC + c];
}

// ---------------- Phi v2: out = 0.5*(h + conv3x3(h) + bias) ----------------
// grid (8 cout-tiles of 16, 32 batch), 256 threads; cin chunks of 16
__global__ __launch_bounds__(256, 2)
void k_conv2(const float* __restrict__ w, const float* __restrict__ bias) {
    __shared__ float sin_[16][324];   // padded 18x18 per cin
    __shared__ float sw[16][144];     // [co][ci*9 + k]
    int ct = blockIdx.x;
    int b = blockIdx.y;
    int tid = threadIdx.x;
    int g = tid & 31;
    int y = g >> 1, x0 = (g & 1) * 8;
    int co_loc = (tid >> 5) * 2;      // warp owns 2 couts (warp-uniform)
    float acc[2][8];
    #pragma unroll
    for (int c = 0; c < 2; c++)
        #pragma unroll
        for (int xi = 0; xi < 8; xi++) acc[c][xi] = 0.f;
    const float* hin = g_h + (size_t)b * CC * 256;

    for (int cc = 0; cc < 8; cc++) {
        int ci0 = cc * 16;
        // stage padded input chunk (zeros on border)
        for (int i = tid; i < 16 * 324; i += 256) {
            int ci = i / 324, p = i - ci * 324;
            int py = p / 18, px = p - py * 18;
            int iy = py - 1, ix = px - 1;
            float v = 0.f;
            if ((unsigned)iy < 16u && (unsigned)ix < 16u)
                v = hin[(ci0 + ci) * 256 + iy * 16 + ix];
            sin_[ci][p] = v;
        }
        // stage weights: 16 co x 144 floats (contiguous per co)
        for (int i = tid; i < 16 * 36; i += 256) {
            int co = i / 36, q = i - co * 36;
            *(float4*)&sw[co][q * 4] =
                *(const float4*)(w + ((size_t)(ct * 16 + co) * CC + ci0) * 9 + q * 4);
        }
        __syncthreads();

        for (int ci = 0; ci < 16; ci++) {
            #pragma unroll
            for (int ky = 0; ky < 3; ky++) {
                float iv[10];
                #pragma unroll
                for (int t = 0; t < 10; t++)
                    iv[t] = sin_[ci][(y + ky) * 18 + x0 + t];
                #pragma unroll
                for (int kx = 0; kx < 3; kx++) {
                    float w0 = sw[co_loc][ci * 9 + ky * 3 + kx];
                    float w1 = sw[co_loc + 1][ci * 9 + ky * 3 + kx];
                    #pragma unroll
                    for (int xi = 0; xi < 8; xi++) {
                        acc[0][xi] += iv[xi + kx] * w0;
                        acc[1][xi] += iv[xi + kx] * w1;
                    }
                }
            }
        }
        __syncthreads();
    }

    #pragma unroll
    for (int co = 0; co < 2; co++) {
        int coid = ct * 16 + co_loc + co;
        float bv = bias[coid];
        #pragma unroll
        for (int xi = 0; xi < 8; xi++) {
            size_t oidx = ((size_t)(b * CC + coid)) * 256 + y * 16 + x0 + xi;
            g_h2[oidx] = 0.5f * (g_h[oidx] + acc[co][xi] + bv);
        }
    }
}

// ---------------- residual update + partial SSE + (last) straight-through out ----------------
__global__ void k_update(const float* __restrict__ f, float* __restrict__ dout, int is_last) {
    int i = blockIdx.x * 256 + threadIdx.x;
    float h2 = g_h2[i];
    float fh = g_fhat[i] + h2;
    g_fhat[i] = fh;
    g_frest[i] = g_frest[i] - h2;
    float fv = f[i];
    float d = fh - fv;
    if (is_last) dout[i] = d + fv;   // mirrors (f_hat - f) + f
    float s = d * d;
    #pragma unroll
    for (int o = 16; o; o >>= 1) s += __shfl_xor_sync(0xffffffffu, s, o);
    __shared__ float ws[8];
    int lane = threadIdx.x & 31, wp = threadIdx.x >> 5;
    if (lane == 0) ws[wp] = s;
    __syncthreads();
    if (threadIdx.x == 0) {
        float t = 0.f;
        #pragma unroll
        for (int k = 0; k < 8; k++) t += ws[k];
        atomicAdd(&g_loss, t);
    }
}

__global__ void k_final(float* dout, int out_size) {
    dout[out_size - 1] = g_loss * (1.25f / (5.f * (float)NUMEL));
}

// ---------------- host ----------------
extern "C" void kernel_launch(void* const* d_in, const int* in_sizes, int n_in,
                              void* d_out, int out_size) {
    const float* f     = (const float*)d_in[0];
    const float* emb   = (const float*)d_in[1];
    const float* phi_w = (const float*)d_in[2];
    const float* phi_b = (const float*)d_in[3];
    float* out = (float*)d_out;

    // Replicate np.linspace(1/12, 11/12, 4) + argmin(|ticks - si/4|) in double.
    double start = 1.0 / 12.0;
    double stop = 1.0 - 1.0 / 12.0;
    double step = (stop - start) / 3.0;
    double ticks[4];
    ticks[0] = 0.0 * step + start;
    ticks[1] = 1.0 * step + start;
    ticks[2] = 2.0 * step + start;
    ticks[3] = stop;
    int kphi[5];
    for (int si = 0; si < 5; si++) {
        double t = (double)si / 4.0;
        int bi = 0;
        double bd = fabs(ticks[0] - t);
        for (int k = 1; k < 4; k++) {
            double d = fabs(ticks[k] - t);
            if (d < bd) { bd = d; bi = k; }
        }
        kphi[si] = bi;
    }

    const int pns[5]    = {1, 2, 4, 8, 16};
    const int vsplit[5] = {64, 64, 64, 16, 8};

    k_esq<<<1024, 256>>>(emb);
    k_init<<<NUMEL / 256, 256>>>(f);

    for (int si = 0; si < 5; si++) {
        int pn = pns[si];
        int s = 16 / pn;
        int N = BB * pn * pn;

        k_pool<<<N, 128>>>(pn, s, N);

        int rb = (N + 127) / 128;
        dim3 grd(rb, vsplit[si]);
        k_argmin2<<<grd, 256>>>(emb, N, VV / vsplit[si]);

        if (si < 4) {
            switch (pn) {
                case 1: k_upsample<1><<<32, 256>>>(emb); break;
                case 2: k_upsample<2><<<32, 256>>>(emb); break;
                case 4: k_upsample<4><<<32, 256>>>(emb); break;
                case 8: k_upsample<8><<<32, 256>>>(emb); break;
            }
        } else {
            k_gather16<<<VV, 128>>>(emb);
        }

        const float* w  = phi_w + (size_t)kphi[si] * CC * CC * 9;
        const float* bb = phi_b + kphi[si] * CC;
        k_conv2<<<dim3(8, 32), 256>>>(w, bb);

        k_update<<<NUMEL / 256, 256>>>(f, out, si == 4 ? 1 : 0);
    }

    k_final<<<1, 1>>>(out, out_size);
}

// round 4
// speedup vs baseline: 2.8520x; 1.3833x over previous
#include <cuda_runtime.h>
#include <cuda_fp16.h>
#include <cstdint>
#include <math.h>

// Problem constants
#define BB 32
#define CC 128
#define VV 8192
#define NUMEL (BB*CC*16*16)   // 1048576

// ---------------- device scratch (no allocs allowed) ----------------
__device__ float g_frest[NUMEL];
__device__ float g_fhat[NUMEL];
__device__ float g_esq[VV];
__device__ unsigned long long g_packed[VV]; // (ordered_score<<32)|idx
__device__ float g_h[NUMEL];
__device__ float g_h2[NUMEL];
__device__ float g_loss;
// fp16 split operands, K=384 layout:
//   emb:  [hi(128) | hi(128) | lo(128)]
//   rest: [hi(128) | lo(128) | hi(128)]
// dot over K=384 = hi*hi + lo*hi + hi*lo
__device__ __align__(16) __half g_embP[(size_t)VV * 384];
__device__ __align__(16) __half g_restP[(size_t)VV * 384];

__device__ __forceinline__ uint32_t smem_to_u32(const void* p) {
    uint32_t a;
    asm("{ .reg .u64 t; cvta.to.shared.u64 t, %1; cvt.u32.u64 %0, t; }" : "=r"(a) : "l"(p));
    return a;
}
__device__ __forceinline__ void ldsm_x4(uint32_t& r0, uint32_t& r1, uint32_t& r2, uint32_t& r3,
                                        uint32_t addr) {
    asm volatile("ldmatrix.sync.aligned.m8n8.x4.shared.b16 {%0,%1,%2,%3}, [%4];"
                 : "=r"(r0), "=r"(r1), "=r"(r2), "=r"(r3) : "r"(addr));
}
__device__ __forceinline__ void mma16816(float* d, const uint32_t* a, const uint32_t* b) {
    asm volatile("mma.sync.aligned.m16n8k16.row.col.f32.f16.f16.f32 "
                 "{%0,%1,%2,%3}, {%4,%5,%6,%7}, {%8,%9}, {%0,%1,%2,%3};"
                 : "+f"(d[0]), "+f"(d[1]), "+f"(d[2]), "+f"(d[3])
                 : "r"(a[0]), "r"(a[1]), "r"(a[2]), "r"(a[3]), "r"(b[0]), "r"(b[1]));
}

// ---------------- init ----------------
__global__ void k_init(const float* __restrict__ f) {
    int i = blockIdx.x * 256 + threadIdx.x;
    g_frest[i] = f[i];
    g_fhat[i] = 0.f;
    if (i == 0) g_loss = 0.f;
}

// ---------------- prep emb: esq + fp16 split [hi|hi|lo] ----------------
__global__ void k_prep_emb(const float* __restrict__ emb) {
    int code = blockIdx.x * 8 + (threadIdx.x >> 5);
    int lane = threadIdx.x & 31;
    float4 v = *(const float4*)(emb + (size_t)code * CC + lane * 4);
    float s = v.x*v.x + v.y*v.y + v.z*v.z + v.w*v.w;
    #pragma unroll
    for (int o = 16; o; o >>= 1) s += __shfl_xor_sync(0xffffffffu, s, o);
    if (lane == 0) g_esq[code] = s;

    __half h0 = __float2half(v.x), h1 = __float2half(v.y);
    __half h2 = __float2half(v.z), h3 = __float2half(v.w);
    __half l0 = __float2half(v.x - __half2float(h0));
    __half l1 = __float2half(v.y - __half2float(h1));
    __half l2 = __float2half(v.z - __half2float(h2));
    __half l3 = __float2half(v.w - __half2float(h3));
    __half2 hA = __halves2half2(h0, h1), hB = __halves2half2(h2, h3);
    __half2 lA = __halves2half2(l0, l1), lB = __halves2half2(l2, l3);
    __half2* base = (__half2*)(g_embP + (size_t)code * 384);
    int c2 = lane * 2;
    base[c2] = hA; base[c2 + 1] = hB;             // [0:128) hi
    base[64 + c2] = hA; base[64 + c2 + 1] = hB;   // [128:256) hi
    base[128 + c2] = lA; base[128 + c2 + 1] = lB; // [256:384) lo
}

// ---------------- pool -> restP split [hi|lo|hi], reset packed ----------------
__global__ void k_pool(int pn, int s, int N) {
    int n = blockIdx.x;
    int c = threadIdx.x;
    int b = n / (pn * pn);
    int rem = n - b * pn * pn;
    int py = rem / pn, px = rem - py * pn;
    const float* base = g_frest + ((size_t)(b * CC + c)) * 256;
    float sum = 0.f;
    for (int dy = 0; dy < s; dy++)
        for (int dx = 0; dx < s; dx++)
            sum += base[(py * s + dy) * 16 + (px * s + dx)];
    float m = sum * (1.f / (float)(s * s));
    __half hi = __float2half(m);
    __half lo = __float2half(m - __half2float(hi));
    __half* dst = g_restP + (size_t)n * 384;
    dst[c] = hi; dst[128 + c] = lo; dst[256 + c] = hi;
    if (c == 0) g_packed[n] = ~0ull;
}

// ---------------- argmin via ldmatrix + mma.sync (HMMA) ----------------
// Dynamic smem: [0:512) esq tile, [512:512+96K) A, [+96K:+192K) B.
// A/B layout: 24 k-chunks of [128 rows][32B], offset ^= (row&7)<<4 swizzle.
#define SM_ESQ 0
#define SM_A 512
#define SM_B (512 + 24*4096)
#define SM_TOTAL (512 + 48*4096)

__global__ __launch_bounds__(256, 1)
void k_argmin_mma(int N, int codesPerBlock) {
    extern __shared__ char smem[];
    uint32_t sb = smem_to_u32(smem);
    float* sEsq = (float*)(smem + SM_ESQ);
    int tid = threadIdx.x;
    int lane = tid & 31, wid = tid >> 5;
    int warp_m = wid >> 2;           // 0..1 : rows warp_m*64..+64
    int warp_n = wid & 3;            // 0..3 : cols warp_n*32..+32
    int n0 = blockIdx.x * 128;
    int v0 = blockIdx.y * codesPerBlock;
    int nTiles = codesPerBlock >> 7;

    // stage A once (rows n0..n0+127, zero-padded)
    for (int i = tid; i < 6144; i += 256) {
        int chunk = i >> 8, rr = (i >> 1) & 127, half = i & 1;
        uint4 v = make_uint4(0, 0, 0, 0);
        int n = n0 + rr;
        if (n < N)
            v = *(const uint4*)((const char*)g_restP + (size_t)n * 768 + chunk * 32 + half * 16);
        uint32_t off = (uint32_t)(chunk * 4096) +
                       (((uint32_t)(rr * 32 + half * 16)) ^ ((uint32_t)(rr & 7) << 4));
        *(uint4*)(smem + SM_A + off) = v;
    }

    const float INF = __int_as_float(0x7f800000);
    float best[8];
    int bidx[8];
    #pragma unroll
    for (int i = 0; i < 8; i++) { best[i] = INF; bidx[i] = 0; }

    // per-thread ldmatrix source offsets (constant across k-chunks)
    uint32_t aoff[4], boff[2];
    #pragma unroll
    for (int mf = 0; mf < 4; mf++) {
        int r = warp_m * 64 + mf * 16 + (lane & 15);
        uint32_t off = (uint32_t)(r * 32 + (lane >> 4) * 16);
        aoff[mf] = sb + SM_A + (off ^ ((uint32_t)(r & 7) << 4));
    }
    #pragma unroll
    for (int nf2 = 0; nf2 < 2; nf2++) {
        int n = warp_n * 32 + nf2 * 16 + ((lane >> 4) << 3) + (lane & 7);
        uint32_t off = (uint32_t)(n * 32 + ((lane >> 3) & 1) * 16);
        boff[nf2] = sb + SM_B + (off ^ ((uint32_t)(n & 7) << 4));
    }

    for (int tt = 0; tt < nTiles; tt++) {
        int c0 = v0 + (tt << 7);
        __syncthreads();   // protect B from previous iteration's readers
        for (int i = tid; i < 6144; i += 256) {
            int chunk = i >> 8, rr = (i >> 1) & 127, half = i & 1;
            uint4 v = *(const uint4*)((const char*)g_embP + (size_t)(c0 + rr) * 768 + chunk * 32 + half * 16);
            uint32_t off = (uint32_t)(chunk * 4096) +
                           (((uint32_t)(rr * 32 + half * 16)) ^ ((uint32_t)(rr & 7) << 4));
            *(uint4*)(smem + SM_B + off) = v;
        }
        if (tid < 128) sEsq[tid] = g_esq[c0 + tid];
        __syncthreads();

        float acc[4][4][4];
        #pragma unroll
        for (int mf = 0; mf < 4; mf++)
            #pragma unroll
            for (int nf = 0; nf < 4; nf++)
                #pragma unroll
                for (int q = 0; q < 4; q++) acc[mf][nf][q] = 0.f;

        #pragma unroll
        for (int kc = 0; kc < 24; kc++) {
            uint32_t cb = (uint32_t)(kc * 4096);
            uint32_t a[4][4], b[4][2];
            #pragma unroll
            for (int mf = 0; mf < 4; mf++)
                ldsm_x4(a[mf][0], a[mf][1], a[mf][2], a[mf][3], aoff[mf] + cb);
            #pragma unroll
            for (int nf2 = 0; nf2 < 2; nf2++) {
                uint32_t r0, r1, r2, r3;
                ldsm_x4(r0, r1, r2, r3, boff[nf2] + cb);
                b[nf2*2][0] = r0; b[nf2*2][1] = r1;
                b[nf2*2+1][0] = r2; b[nf2*2+1][1] = r3;
            }
            #pragma unroll
            for (int mf = 0; mf < 4; mf++)
                #pragma unroll
                for (int nf = 0; nf < 4; nf++)
                    mma16816(acc[mf][nf], a[mf], b[nf]);
        }

        // epilogue: score + running argmin (strict <, ascending col order)
        #pragma unroll
        for (int nf = 0; nf < 4; nf++) {
            int colL = warp_n * 32 + nf * 8 + 2 * (lane & 3);
            float es0 = sEsq[colL], es1 = sEsq[colL + 1];
            int cg = c0 + colL;
            #pragma unroll
            for (int mf = 0; mf < 4; mf++) {
                float* d = acc[mf][nf];
                int s0 = mf * 2, s1 = mf * 2 + 1;
                float v;
                v = fmaf(-2.f, d[0], es0); if (v < best[s0]) { best[s0] = v; bidx[s0] = cg; }
                v = fmaf(-2.f, d[1], es1); if (v < best[s0]) { best[s0] = v; bidx[s0] = cg + 1; }
                v = fmaf(-2.f, d[2], es0); if (v < best[s1]) { best[s1] = v; bidx[s1] = cg; }
                v = fmaf(-2.f, d[3], es1); if (v < best[s1]) { best[s1] = v; bidx[s1] = cg + 1; }
            }
        }
    }

    // combine across the 4 lanes sharing each row (tie -> smaller index)
    #pragma unroll
    for (int o = 1; o <= 2; o <<= 1) {
        #pragma unroll
        for (int s = 0; s < 8; s++) {
            float so = __shfl_xor_sync(0xffffffffu, best[s], o);
            int io = __shfl_xor_sync(0xffffffffu, bidx[s], o);
            if (so < best[s] || (so == best[s] && io < bidx[s])) { best[s] = so; bidx[s] = io; }
        }
    }
    if ((lane & 3) == 0) {
        #pragma unroll
        for (int s = 0; s < 8; s++) {
            int mf = s >> 1, h = s & 1;
            int r = n0 + warp_m * 64 + mf * 16 + (lane >> 2) + h * 8;
            if (r < N) {
                unsigned u = __float_as_uint(best[s]);
                u = (u & 0x80000000u) ? ~u : (u | 0x80000000u);
                unsigned long long p = ((unsigned long long)u << 32) | (unsigned)bidx[s];
                atomicMin(&g_packed[r], p);
            }
        }
    }
}

// ---------------- bicubic weights ----------------
template <int PN>
__device__ __forceinline__ void cubic_weights(int j, float* w) {
    float sf = (j + 0.5f) * ((float)PN / 16.f) - 0.5f;
    float tot = 0.f;
    #pragma unroll
    for (int i = 0; i < PN; i++) {
        float x = fabsf(sf - (float)i);
        float v = 0.f;
        if (x <= 1.f)      v = ((1.5f * x - 2.5f) * x) * x + 1.f;
        else if (x < 2.f)  v = ((-0.5f * x + 2.5f) * x - 4.f) * x + 2.f;
        w[i] = v;
        tot += v;
    }
    float r = 1.f / tot;
    #pragma unroll
    for (int i = 0; i < PN; i++) w[i] *= r;
}

// ---------------- gather + bicubic upsample ----------------
template <int PN>
__global__ void k_upsample(const float* __restrict__ emb) {
    const int NP = PN * PN;
    __shared__ float g[64][128];
    __shared__ float wtab[16][8];
    int b = blockIdx.x;
    for (int i = threadIdx.x; i < NP * CC; i += 256) {
        int p = i >> 7, c = i & 127;
        unsigned idx = (unsigned)(g_packed[b * NP + p] & 0xffffffffu);
        g[p][c] = emb[(size_t)idx * CC + c];
    }
    if (threadIdx.x < 16) cubic_weights<PN>(threadIdx.x, &wtab[threadIdx.x][0]);
    __syncthreads();
    for (int o = threadIdx.x; o < 16 * 16 * CC; o += 256) {
        int c = o & 127;
        int sp = o >> 7;
        int x = sp & 15, y = sp >> 4;
        float acc = 0.f;
        #pragma unroll
        for (int iy = 0; iy < PN; iy++) {
            float ra = 0.f;
            #pragma unroll
            for (int ix = 0; ix < PN; ix++)
                ra += wtab[x][ix] * g[iy * PN + ix][c];
            acc += wtab[y][iy] * ra;
        }
        g_h[((size_t)(b * CC + c)) * 256 + y * 16 + x] = acc;
    }
}

__global__ void k_gather16(const float* __restrict__ emb) {
    int n = blockIdx.x;
    int c = threadIdx.x;
    unsigned idx = (unsigned)(g_packed[n] & 0xffffffffu);
    int b = n >> 8, y = (n >> 4) & 15, x = n & 15;
    g_h[((size_t)(b * CC + c)) * 256 + y * 16 + x] = emb[(size_t)idx * CC + c];
}

// ---------------- Phi conv ----------------
__global__ __launch_bounds__(256, 2)
void k_conv2(const float* __restrict__ w, const float* __restrict__ bias) {
    __shared__ float sin_[16][324];
    __shared__ float sw[16][144];
    int ct = blockIdx.x;
    int b = blockIdx.y;
    int tid = threadIdx.x;
    int g = tid & 31;
    int y = g >> 1, x0 = (g & 1) * 8;
    int co_loc = (tid >> 5) * 2;
    float acc[2][8];
    #pragma unroll
    for (int c = 0; c < 2; c++)
        #pragma unroll
        for (int xi = 0; xi < 8; xi++) acc[c][xi] = 0.f;
    const float* hin = g_h + (size_t)b * CC * 256;

    for (int cc = 0; cc < 8; cc++) {
        int ci0 = cc * 16;
        for (int i = tid; i < 16 * 324; i += 256) {
            int ci = i / 324, p = i - ci * 324;
            int py = p / 18, px = p - py * 18;
            int iy = py - 1, ix = px - 1;
            float v = 0.f;
            if ((unsigned)iy < 16u && (unsigned)ix < 16u)
                v = hin[(ci0 + ci) * 256 + iy * 16 + ix];
            sin_[ci][p] = v;
        }
        for (int i = tid; i < 16 * 36; i += 256) {
            int co = i / 36, q = i - co * 36;
            *(float4*)&sw[co][q * 4] =
                *(const float4*)(w + ((size_t)(ct * 16 + co) * CC + ci0) * 9 + q * 4);
        }
        __syncthreads();
        for (int ci = 0; ci < 16; ci++) {
            #pragma unroll
            for (int ky = 0; ky < 3; ky++) {
                float iv[10];
                #pragma unroll
                for (int t = 0; t < 10; t++)
                    iv[t] = sin_[ci][(y + ky) * 18 + x0 + t];
                #pragma unroll
                for (int kx = 0; kx < 3; kx++) {
                    float w0 = sw[co_loc][ci * 9 + ky * 3 + kx];
                    float w1 = sw[co_loc + 1][ci * 9 + ky * 3 + kx];
                    #pragma unroll
                    for (int xi = 0; xi < 8; xi++) {
                        acc[0][xi] += iv[xi + kx] * w0;
                        acc[1][xi] += iv[xi + kx] * w1;
                    }
                }
            }
        }
        __syncthreads();
    }
    #pragma unroll
    for (int co = 0; co < 2; co++) {
        int coid = ct * 16 + co_loc + co;
        float bv = bias[coid];
        #pragma unroll
        for (int xi = 0; xi < 8; xi++) {
            size_t oidx = ((size_t)(b * CC + coid)) * 256 + y * 16 + x0 + xi;
            g_h2[oidx] = 0.5f * (g_h[oidx] + acc[co][xi] + bv);
        }
    }
}

// ---------------- residual update + SSE + straight-through out ----------------
__global__ void k_update(const float* __restrict__ f, float* __restrict__ dout, int is_last) {
    int i = blockIdx.x * 256 + threadIdx.x;
    float h2 = g_h2[i];
    float fh = g_fhat[i] + h2;
    g_fhat[i] = fh;
    g_frest[i] = g_frest[i] - h2;
    float fv = f[i];
    float d = fh - fv;
    if (is_last) dout[i] = d + fv;
    float s = d * d;
    #pragma unroll
    for (int o = 16; o; o >>= 1) s += __shfl_xor_sync(0xffffffffu, s, o);
    __shared__ float ws[8];
    int lane = threadIdx.x & 31, wp = threadIdx.x >> 5;
    if (lane == 0) ws[wp] = s;
    __syncthreads();
    if (threadIdx.x == 0) {
        float t = 0.f;
        #pragma unroll
        for (int k = 0; k < 8; k++) t += ws[k];
        atomicAdd(&g_loss, t);
    }
}

__global__ void k_final(float* dout, int out_size) {
    dout[out_size - 1] = g_loss * (1.25f / (5.f * (float)NUMEL));
}

// ---------------- host ----------------
extern "C" void kernel_launch(void* const* d_in, const int* in_sizes, int n_in,
                              void* d_out, int out_size) {
    const float* f     = (const float*)d_in[0];
    const float* emb   = (const float*)d_in[1];
    const float* phi_w = (const float*)d_in[2];
    const float* phi_b = (const float*)d_in[3];
    float* out = (float*)d_out;

    cudaFuncSetAttribute(k_argmin_mma, cudaFuncAttributeMaxDynamicSharedMemorySize, SM_TOTAL);

    // Replicate np.linspace(1/12, 11/12, 4) + argmin(|ticks - si/4|) in double.
    double start = 1.0 / 12.0;
    double stop = 1.0 - 1.0 / 12.0;
    double step = (stop - start) / 3.0;
    double ticks[4];
    ticks[0] = 0.0 * step + start;
    ticks[1] = 1.0 * step + start;
    ticks[2] = 2.0 * step + start;
    ticks[3] = stop;
    int kphi[5];
    for (int si = 0; si < 5; si++) {
        double t = (double)si / 4.0;
        int bi = 0;
        double bd = fabs(ticks[0] - t);
        for (int k = 1; k < 4; k++) {
            double d = fabs(ticks[k] - t);
            if (d < bd) { bd = d; bi = k; }
        }
        kphi[si] = bi;
    }

    const int pns[5]    = {1, 2, 4, 8, 16};
    const int vsplit[5] = {64, 64, 32, 16, 4};

    k_prep_emb<<<VV / 8, 256>>>(emb);
    k_init<<<NUMEL / 256, 256>>>(f);

    for (int si = 0; si < 5; si++) {
        int pn = pns[si];
        int s = 16 / pn;
        int N = BB * pn * pn;

        k_pool<<<N, 128>>>(pn, s, N);

        int rb = (N + 127) / 128;
        dim3 grd(rb, vsplit[si]);
        k_argmin_mma<<<grd, 256, SM_TOTAL>>>(N, VV / vsplit[si]);

        if (si < 4) {
            switch (pn) {
                case 1: k_upsample<1><<<32, 256>>>(emb); break;
                case 2: k_upsample<2><<<32, 256>>>(emb); break;
                case 4: k_upsample<4><<<32, 256>>>(emb); break;
                case 8: k_upsample<8><<<32, 256>>>(emb); break;
            }
        } else {
            k_gather16<<<VV, 128>>>(emb);
        }

        const float* w  = phi_w + (size_t)kphi[si] * CC * CC * 9;
        const float* bb = phi_b + kphi[si] * CC;
        k_conv2<<<dim3(8, 32), 256>>>(w, bb);

        k_update<<<NUMEL / 256, 256>>>(f, out, si == 4 ? 1 : 0);
    }

    k_final<<<1, 1>>>(out, out_size);
}

// round 6
// speedup vs baseline: 3.6381x; 1.2756x over previous
#include <cuda_runtime.h>
#include <cuda_fp16.h>
#include <cstdint>
#include <math.h>

// Problem constants
#define BB 32
#define CC 128
#define VV 8192
#define NUMEL (BB*CC*16*16)   // 1048576

// ---------------- device scratch (no allocs allowed) ----------------
__device__ float g_frest[NUMEL];
__device__ float g_fhat[NUMEL];
__device__ float g_esq[VV];
__device__ unsigned long long g_packed[VV]; // (ordered_score<<32)|idx
__device__ float g_h[NUMEL];
__device__ float g_h2[NUMEL];
__device__ float g_loss;
// fp16 split operands for argmin, K=384:
//   emb:  [hi|hi|lo]   rest: [hi|lo|hi]   -> dot = hi*hi + lo*hi + hi*lo
__device__ __align__(16) __half g_embP[(size_t)VV * 384];
__device__ __align__(16) __half g_restP[(size_t)VV * 384];
// conv operands:
//  hT[b][sp=y*16+x][plane]: plane<128 = hi(h[ci]), 128..255 = lo(h[ci])
__device__ __align__(16) __half g_hT[(size_t)BB * 256 * 256];
//  wP[phi][tap][cout][384]: plane<128 hi(w), <256 hi(w), <384 lo(w)
__device__ __align__(16) __half g_wP[(size_t)4 * 9 * 128 * 384];

__device__ __forceinline__ uint32_t smem_to_u32(const void* p) {
    uint32_t a;
    asm("{ .reg .u64 t; cvta.to.shared.u64 t, %1; cvt.u32.u64 %0, t; }" : "=r"(a) : "l"(p));
    return a;
}
__device__ __forceinline__ void ldsm_x4(uint32_t& r0, uint32_t& r1, uint32_t& r2, uint32_t& r3,
                                        uint32_t addr) {
    asm volatile("ldmatrix.sync.aligned.m8n8.x4.shared.b16 {%0,%1,%2,%3}, [%4];"
                 : "=r"(r0), "=r"(r1), "=r"(r2), "=r"(r3) : "r"(addr));
}
__device__ __forceinline__ void mma16816(float* d, const uint32_t* a, const uint32_t* b) {
    asm volatile("mma.sync.aligned.m16n8k16.row.col.f32.f16.f16.f32 "
                 "{%0,%1,%2,%3}, {%4,%5,%6,%7}, {%8,%9}, {%0,%1,%2,%3};"
                 : "+f"(d[0]), "+f"(d[1]), "+f"(d[2]), "+f"(d[3])
                 : "r"(a[0]), "r"(a[1]), "r"(a[2]), "r"(a[3]), "r"(b[0]), "r"(b[1]));
}

// ---------------- init ----------------
__global__ void k_init(const float* __restrict__ f) {
    int i = blockIdx.x * 256 + threadIdx.x;
    g_frest[i] = f[i];
    g_fhat[i] = 0.f;
    if (i == 0) g_loss = 0.f;
}

// ---------------- prep emb: esq + fp16 split [hi|hi|lo] ----------------
__global__ void k_prep_emb(const float* __restrict__ emb) {
    int code = blockIdx.x * 8 + (threadIdx.x >> 5);
    int lane = threadIdx.x & 31;
    float4 v = *(const float4*)(emb + (size_t)code * CC + lane * 4);
    float s = v.x*v.x + v.y*v.y + v.z*v.z + v.w*v.w;
    #pragma unroll
    for (int o = 16; o; o >>= 1) s += __shfl_xor_sync(0xffffffffu, s, o);
    if (lane == 0) g_esq[code] = s;

    __half h0 = __float2half(v.x), h1 = __float2half(v.y);
    __half h2 = __float2half(v.z), h3 = __float2half(v.w);
    __half l0 = __float2half(v.x - __half2float(h0));
    __half l1 = __float2half(v.y - __half2float(h1));
    __half l2 = __float2half(v.z - __half2float(h2));
    __half l3 = __float2half(v.w - __half2float(h3));
    __half2 hA = __halves2half2(h0, h1), hB = __halves2half2(h2, h3);
    __half2 lA = __halves2half2(l0, l1), lB = __halves2half2(l2, l3);
    __half2* base = (__half2*)(g_embP + (size_t)code * 384);
    int c2 = lane * 2;
    base[c2] = hA; base[c2 + 1] = hB;
    base[64 + c2] = hA; base[64 + c2 + 1] = hB;
    base[128 + c2] = lA; base[128 + c2 + 1] = lB;
}

// ---------------- prep weights: wP[phi][tap][cout][384] fp16 [hi|hi|lo] ----------------
__global__ void k_prep_w(const float* __restrict__ phi_w) {
    int id = blockIdx.x;            // 4*9*128
    int cout = id & 127;
    int tap = (id >> 7) % 9;
    int phi = id / (9 * 128);
    int ci = threadIdx.x;
    float w = phi_w[(((size_t)phi * 128 + cout) * 128 + ci) * 9 + tap];
    __half hi = __float2half(w);
    __half lo = __float2half(w - __half2float(hi));
    __half* dst = g_wP + (((size_t)phi * 9 + tap) * 128 + cout) * 384;
    dst[ci] = hi; dst[128 + ci] = hi; dst[256 + ci] = lo;
}

// ---------------- pool -> restP split [hi|lo|hi], reset packed ----------------
__global__ void k_pool(int pn, int s, int N) {
    int n = blockIdx.x;
    int c = threadIdx.x;
    int b = n / (pn * pn);
    int rem = n - b * pn * pn;
    int py = rem / pn, px = rem - py * pn;
    const float* base = g_frest + ((size_t)(b * CC + c)) * 256;
    float sum = 0.f;
    for (int dy = 0; dy < s; dy++)
        for (int dx = 0; dx < s; dx++)
            sum += base[(py * s + dy) * 16 + (px * s + dx)];
    float m = sum * (1.f / (float)(s * s));
    __half hi = __float2half(m);
    __half lo = __float2half(m - __half2float(hi));
    __half* dst = g_restP + (size_t)n * 384;
    dst[c] = hi; dst[128 + c] = lo; dst[256 + c] = hi;
    if (c == 0) g_packed[n] = ~0ull;
}

// ---------------- argmin via ldmatrix + mma.sync (HMMA) ----------------
#define SM_ESQ 0
#define SM_A 512
#define SM_B (512 + 24*4096)
#define SM_TOTAL (512 + 48*4096)

__global__ __launch_bounds__(256, 1)
void k_argmin_mma(int N, int codesPerBlock) {
    extern __shared__ char smem[];
    uint32_t sb = smem_to_u32(smem);
    float* sEsq = (float*)(smem + SM_ESQ);
    int tid = threadIdx.x;
    int lane = tid & 31, wid = tid >> 5;
    int warp_m = wid >> 2;
    int warp_n = wid & 3;
    int n0 = blockIdx.x * 128;
    int v0 = blockIdx.y * codesPerBlock;
    int nTiles = codesPerBlock >> 7;

    for (int i = tid; i < 6144; i += 256) {
        int chunk = i >> 8, rr = (i >> 1) & 127, half = i & 1;
        uint4 v = make_uint4(0, 0, 0, 0);
        int n = n0 + rr;
        if (n < N)
            v = *(const uint4*)((const char*)g_restP + (size_t)n * 768 + chunk * 32 + half * 16);
        uint32_t off = (uint32_t)(chunk * 4096) +
                       (((uint32_t)(rr * 32 + half * 16)) ^ ((uint32_t)(rr & 7) << 4));
        *(uint4*)(smem + SM_A + off) = v;
    }

    const float INF = __int_as_float(0x7f800000);
    float best[8];
    int bidx[8];
    #pragma unroll
    for (int i = 0; i < 8; i++) { best[i] = INF; bidx[i] = 0; }

    uint32_t aoff[4], boff[2];
    #pragma unroll
    for (int mf = 0; mf < 4; mf++) {
        int r = warp_m * 64 + mf * 16 + (lane & 15);
        uint32_t off = (uint32_t)(r * 32 + (lane >> 4) * 16);
        aoff[mf] = sb + SM_A + (off ^ ((uint32_t)(r & 7) << 4));
    }
    #pragma unroll
    for (int nf2 = 0; nf2 < 2; nf2++) {
        int n = warp_n * 32 + nf2 * 16 + ((lane >> 4) << 3) + (lane & 7);
        uint32_t off = (uint32_t)(n * 32 + ((lane >> 3) & 1) * 16);
        boff[nf2] = sb + SM_B + (off ^ ((uint32_t)(n & 7) << 4));
    }

    for (int tt = 0; tt < nTiles; tt++) {
        int c0 = v0 + (tt << 7);
        __syncthreads();
        for (int i = tid; i < 6144; i += 256) {
            int chunk = i >> 8, rr = (i >> 1) & 127, half = i & 1;
            uint4 v = *(const uint4*)((const char*)g_embP + (size_t)(c0 + rr) * 768 + chunk * 32 + half * 16);
            uint32_t off = (uint32_t)(chunk * 4096) +
                           (((uint32_t)(rr * 32 + half * 16)) ^ ((uint32_t)(rr & 7) << 4));
            *(uint4*)(smem + SM_B + off) = v;
        }
        if (tid < 128) sEsq[tid] = g_esq[c0 + tid];
        __syncthreads();

        float acc[4][4][4];
        #pragma unroll
        for (int mf = 0; mf < 4; mf++)
            #pragma unroll
            for (int nf = 0; nf < 4; nf++)
                #pragma unroll
                for (int q = 0; q < 4; q++) acc[mf][nf][q] = 0.f;

        #pragma unroll
        for (int kc = 0; kc < 24; kc++) {
            uint32_t cb = (uint32_t)(kc * 4096);
            uint32_t a[4][4], b[4][2];
            #pragma unroll
            for (int mf = 0; mf < 4; mf++)
                ldsm_x4(a[mf][0], a[mf][1], a[mf][2], a[mf][3], aoff[mf] + cb);
            #pragma unroll
            for (int nf2 = 0; nf2 < 2; nf2++) {
                uint32_t r0, r1, r2, r3;
                ldsm_x4(r0, r1, r2, r3, boff[nf2] + cb);
                b[nf2*2][0] = r0; b[nf2*2][1] = r1;
                b[nf2*2+1][0] = r2; b[nf2*2+1][1] = r3;
            }
            #pragma unroll
            for (int mf = 0; mf < 4; mf++)
                #pragma unroll
                for (int nf = 0; nf < 4; nf++)
                    mma16816(acc[mf][nf], a[mf], b[nf]);
        }

        #pragma unroll
        for (int nf = 0; nf < 4; nf++) {
            int colL = warp_n * 32 + nf * 8 + 2 * (lane & 3);
            float es0 = sEsq[colL], es1 = sEsq[colL + 1];
            int cg = c0 + colL;
            #pragma unroll
            for (int mf = 0; mf < 4; mf++) {
                float* d = acc[mf][nf];
                int s0 = mf * 2, s1 = mf * 2 + 1;
                float v;
                v = fmaf(-2.f, d[0], es0); if (v < best[s0]) { best[s0] = v; bidx[s0] = cg; }
                v = fmaf(-2.f, d[1], es1); if (v < best[s0]) { best[s0] = v; bidx[s0] = cg + 1; }
                v = fmaf(-2.f, d[2], es0); if (v < best[s1]) { best[s1] = v; bidx[s1] = cg; }
                v = fmaf(-2.f, d[3], es1); if (v < best[s1]) { best[s1] = v; bidx[s1] = cg + 1; }
            }
        }
    }

    #pragma unroll
    for (int o = 1; o <= 2; o <<= 1) {
        #pragma unroll
        for (int s = 0; s < 8; s++) {
            float so = __shfl_xor_sync(0xffffffffu, best[s], o);
            int io = __shfl_xor_sync(0xffffffffu, bidx[s], o);
            if (so < best[s] || (so == best[s] && io < bidx[s])) { best[s] = so; bidx[s] = io; }
        }
    }
    if ((lane & 3) == 0) {
        #pragma unroll
        for (int s = 0; s < 8; s++) {
            int mf = s >> 1, h = s & 1;
            int r = n0 + warp_m * 64 + mf * 16 + (lane >> 2) + h * 8;
            if (r < N) {
                unsigned u = __float_as_uint(best[s]);
                u = (u & 0x80000000u) ? ~u : (u | 0x80000000u);
                unsigned long long p = ((unsigned long long)u << 32) | (unsigned)bidx[s];
                atomicMin(&g_packed[r], p);
            }
        }
    }
}

// ---------------- bicubic weights ----------------
template <int PN>
__device__ __forceinline__ void cubic_weights(int j, float* w) {
    float sf = (j + 0.5f) * ((float)PN / 16.f) - 0.5f;
    float tot = 0.f;
    #pragma unroll
    for (int i = 0; i < PN; i++) {
        float x = fabsf(sf - (float)i);
        float v = 0.f;
        if (x <= 1.f)      v = ((1.5f * x - 2.5f) * x) * x + 1.f;
        else if (x < 2.f)  v = ((-0.5f * x + 2.5f) * x - 4.f) * x + 2.f;
        w[i] = v;
        tot += v;
    }
    float r = 1.f / tot;
    #pragma unroll
    for (int i = 0; i < PN; i++) w[i] *= r;
}

// ---------------- gather + bicubic upsample (also writes hT fp16 split) ----------------
template <int PN>
__global__ void k_upsample(const float* __restrict__ emb) {
    const int NP = PN * PN;
    __shared__ float g[64][128];
    __shared__ float wtab[16][8];
    int b = blockIdx.x;
    for (int i = threadIdx.x; i < NP * CC; i += 256) {
        int p = i >> 7, c = i & 127;
        unsigned idx = (unsigned)(g_packed[b * NP + p] & 0xffffffffu);
        g[p][c] = emb[(size_t)idx * CC + c];
    }
    if (threadIdx.x < 16) cubic_weights<PN>(threadIdx.x, &wtab[threadIdx.x][0]);
    __syncthreads();
    for (int o = threadIdx.x; o < 16 * 16 * CC; o += 256) {
        int c = o & 127;
        int sp = o >> 7;
        int x = sp & 15, y = sp >> 4;
        float acc = 0.f;
        #pragma unroll
        for (int iy = 0; iy < PN; iy++) {
            float ra = 0.f;
            #pragma unroll
            for (int ix = 0; ix < PN; ix++)
                ra += wtab[x][ix] * g[iy * PN + ix][c];
            acc += wtab[y][iy] * ra;
        }
        g_h[((size_t)(b * CC + c)) * 256 + y * 16 + x] = acc;
        __half hi = __float2half(acc);
        __half lo = __float2half(acc - __half2float(hi));
        __half* ht = g_hT + ((size_t)b * 256 + sp) * 256;
        ht[c] = hi; ht[128 + c] = lo;
    }
}

__global__ void k_gather16(const float* __restrict__ emb) {
    int n = blockIdx.x;
    int c = threadIdx.x;
    unsigned idx = (unsigned)(g_packed[n] & 0xffffffffu);
    int b = n >> 8, y = (n >> 4) & 15, x = n & 15;
    float v = emb[(size_t)idx * CC + c];
    g_h[((size_t)(b * CC + c)) * 256 + y * 16 + x] = v;
    __half hi = __float2half(v);
    __half lo = __float2half(v - __half2float(hi));
    __half* ht = g_hT + ((size_t)b * 256 + (n & 255)) * 256;
    ht[c] = hi; ht[128 + c] = lo;
}

// ---------------- Phi conv via HMMA tap-decomposed implicit GEMM ----------------
// grid (4 mq, 32 b). Block: 64 spatial rows x 128 couts, K=384 in 6 chunks of 64.
// smem: sIn[108 halo rows][64 planes] (13824B) + sW[9 taps][128 cout][64] (147456B)
#define SM_IN 0
#define SM_W 13824
#define SM_CONV (13824 + 147456)

__global__ __launch_bounds__(256, 1)
void k_conv_mma(int phi, const float* __restrict__ bias) {
    extern __shared__ char smem[];
    uint32_t sb = smem_to_u32(smem);
    int tid = threadIdx.x;
    int lane = tid & 31, wid = tid >> 5;
    int mq = blockIdx.x;
    int b = blockIdx.y;
    int warp_m = wid >> 2, warp_n = wid & 3;

    const __half* wSrc = g_wP + (size_t)phi * 9 * 128 * 384;
    const __half* hTb = g_hT + (size_t)b * 256 * 256;

    float acc[2][4][4];
    #pragma unroll
    for (int mf = 0; mf < 2; mf++)
        #pragma unroll
        for (int nf = 0; nf < 4; nf++)
            #pragma unroll
            for (int q = 0; q < 4; q++) acc[mf][nf][q] = 0.f;

    int r0[2];
    #pragma unroll
    for (int mf = 0; mf < 2; mf++) {
        int mloc = warp_m * 32 + mf * 16 + (lane & 15);
        r0[mf] = (mloc >> 4) * 18 + (mloc & 15);
    }
    int acol = (lane >> 4) * 16;
    int nrow[2];
    #pragma unroll
    for (int nf2 = 0; nf2 < 2; nf2++)
        nrow[nf2] = warp_n * 32 + nf2 * 16 + ((lane >> 4) << 3) + (lane & 7);
    int bcol = ((lane >> 3) & 1) * 16;

    const int dts[9] = {0, 1, 2, 18, 19, 20, 36, 37, 38};

    for (int kc = 0; kc < 6; kc++) {
        int srcPlane = (kc < 4 ? kc : kc - 4) * 64;
        __syncthreads();
        // stage input halo chunk: 108 rows x 64 planes
        for (int i = tid; i < 864; i += 256) {
            int lr = i >> 3, c16 = i & 7;
            int ly = lr / 18, lx = lr - ly * 18;
            int iy = mq * 4 + ly - 1, ix = lx - 1;
            uint4 v = make_uint4(0, 0, 0, 0);
            if ((unsigned)iy < 16u && (unsigned)ix < 16u)
                v = *(const uint4*)(hTb + ((size_t)(iy * 16 + ix)) * 256 + srcPlane + c16 * 8);
            *(uint4*)(smem + SM_IN + lr * 128 + ((c16 * 16) ^ ((lr & 7) << 4))) = v;
        }
        // stage all 9 taps' weight chunk: 9 x 128 x 64
        for (int i = tid; i < 9216; i += 256) {
            int tap = i >> 10, r = (i >> 3) & 127, c16 = i & 7;
            uint4 v = *(const uint4*)(wSrc + ((size_t)tap * 128 + r) * 384 + kc * 64 + c16 * 8);
            *(uint4*)(smem + SM_W + tap * 16384 + r * 128 + ((c16 * 16) ^ ((r & 7) << 4))) = v;
        }
        __syncthreads();

        for (int tap = 0; tap < 9; tap++) {
            int dt = dts[tap];
            uint32_t wbase = sb + SM_W + tap * 16384;
            #pragma unroll
            for (int kb = 0; kb < 4; kb++) {
                uint32_t a[2][4], bf[4][2];
                #pragma unroll
                for (int mf = 0; mf < 2; mf++) {
                    int rA = r0[mf] + dt;
                    uint32_t addr = sb + SM_IN + rA * 128 +
                                    (((uint32_t)(kb * 32 + acol)) ^ ((uint32_t)(rA & 7) << 4));
                    ldsm_x4(a[mf][0], a[mf][1], a[mf][2], a[mf][3], addr);
                }
                #pragma unroll
                for (int nf2 = 0; nf2 < 2; nf2++) {
                    int nr = nrow[nf2];
                    uint32_t addr = wbase + nr * 128 +
                                    (((uint32_t)(kb * 32 + bcol)) ^ ((uint32_t)(nr & 7) << 4));
                    uint32_t q0, q1, q2, q3;
                    ldsm_x4(q0, q1, q2, q3, addr);
                    bf[nf2*2][0] = q0; bf[nf2*2][1] = q1;
                    bf[nf2*2+1][0] = q2; bf[nf2*2+1][1] = q3;
                }
                #pragma unroll
                for (int mf = 0; mf < 2; mf++)
                    #pragma unroll
                    for (int nf = 0; nf < 4; nf++)
                        mma16816(acc[mf][nf], a[mf], bf[nf]);
            }
        }
    }

    // epilogue: g_h2 = 0.5*(g_h + conv + bias)
    #pragma unroll
    for (int nf = 0; nf < 4; nf++) {
        int c = warp_n * 32 + nf * 8 + (lane & 3) * 2;
        float bv0 = __ldg(&bias[c]), bv1 = __ldg(&bias[c + 1]);
        #pragma unroll
        for (int mf = 0; mf < 2; mf++) {
            #pragma unroll
            for (int h = 0; h < 2; h++) {
                int m = warp_m * 32 + mf * 16 + (lane >> 2) + h * 8;
                int sp = mq * 64 + m;
                size_t i0 = ((size_t)(b * CC + c)) * 256 + sp;
                size_t i1 = i0 + 256;
                g_h2[i0] = 0.5f * (g_h[i0] + acc[mf][nf][h * 2] + bv0);
                g_h2[i1] = 0.5f * (g_h[i1] + acc[mf][nf][h * 2 + 1] + bv1);
            }
        }
    }
}

// ---------------- residual update + SSE + straight-through out ----------------
__global__ void k_update(const float* __restrict__ f, float* __restrict__ dout, int is_last) {
    int i = blockIdx.x * 256 + threadIdx.x;
    float h2 = g_h2[i];
    float fh = g_fhat[i] + h2;
    g_fhat[i] = fh;
    g_frest[i] = g_frest[i] - h2;
    float fv = f[i];
    float d = fh - fv;
    if (is_last) dout[i] = d + fv;
    float s = d * d;
    #pragma unroll
    for (int o = 16; o; o >>= 1) s += __shfl_xor_sync(0xffffffffu, s, o);
    __shared__ float ws[8];
    int lane = threadIdx.x & 31, wp = threadIdx.x >> 5;
    if (lane == 0) ws[wp] = s;
    __syncthreads();
    if (threadIdx.x == 0) {
        float t = 0.f;
        #pragma unroll
        for (int k = 0; k < 8; k++) t += ws[k];
        atomicAdd(&g_loss, t);
    }
}

__global__ void k_final(float* dout, int out_size) {
    dout[out_size - 1] = g_loss * (1.25f / (5.f * (float)NUMEL));
}

// ---------------- host ----------------
extern "C" void kernel_launch(void* const* d_in, const int* in_sizes, int n_in,
                              void* d_out, int out_size) {
    const float* f     = (const float*)d_in[0];
    const float* emb   = (const float*)d_in[1];
    const float* phi_w = (const float*)d_in[2];
    const float* phi_b = (const float*)d_in[3];
    float* out = (float*)d_out;

    cudaFuncSetAttribute(k_argmin_mma, cudaFuncAttributeMaxDynamicSharedMemorySize, SM_TOTAL);
    cudaFuncSetAttribute(k_conv_mma, cudaFuncAttributeMaxDynamicSharedMemorySize, SM_CONV);

    // Replicate np.linspace(1/12, 11/12, 4) + argmin(|ticks - si/4|) in double.
    double start = 1.0 / 12.0;
    double stop = 1.0 - 1.0 / 12.0;
    double step = (stop - start) / 3.0;
    double ticks[4];
    ticks[0] = 0.0 * step + start;
    ticks[1] = 1.0 * step + start;
    ticks[2] = 2.0 * step + start;
    ticks[3] = stop;
    int kphi[5];
    for (int si = 0; si < 5; si++) {
        double t = (double)si / 4.0;
        int bi = 0;
        double bd = fabs(ticks[0] - t);
        for (int k = 1; k < 4; k++) {
            double d = fabs(ticks[k] - t);
            if (d < bd) { bd = d; bi = k; }
        }
        kphi[si] = bi;
    }

    const int pns[5]    = {1, 2, 4, 8, 16};
    const int vsplit[5] = {64, 64, 32, 16, 4};

    k_prep_emb<<<VV / 8, 256>>>(emb);
    k_prep_w<<<4 * 9 * 128, 128>>>(phi_w);
    k_init<<<NUMEL / 256, 256>>>(f);

    for (int si = 0; si < 5; si++) {
        int pn = pns[si];
        int s = 16 / pn;
        int N = BB * pn * pn;

        k_pool<<<N, 128>>>(pn, s, N);

        int rb = (N + 127) / 128;
        dim3 grd(rb, vsplit[si]);
        k_argmin_mma<<<grd, 256, SM_TOTAL>>>(N, VV / vsplit[si]);

        if (si < 4) {
            switch (pn) {
                case 1: k_upsample<1><<<32, 256>>>(emb); break;
                case 2: k_upsample<2><<<32, 256>>>(emb); break;
                case 4: k_upsample<4><<<32, 256>>>(emb); break;
                case 8: k_upsample<8><<<32, 256>>>(emb); break;
            }
        } else {
            k_gather16<<<VV, 128>>>(emb);
        }

        k_conv_mma<<<dim3(4, 32), 256, SM_CONV>>>(kphi[si], phi_b + kphi[si] * 128);

        k_update<<<NUMEL / 256, 256>>>(f, out, si == 4 ? 1 : 0);
    }

    k_final<<<1, 1>>>(out, out_size);
}

// round 9
// speedup vs baseline: 4.7932x; 1.3175x over previous
#include <cuda_runtime.h>
#include <cuda_fp16.h>
#include <cstdint>
#include <math.h>

// Problem constants
#define BB 32
#define CC 128
#define VV 8192
#define NUMEL (BB*CC*16*16)   // 1048576

// ---------------- device scratch (no allocs allowed) ----------------
__device__ float g_frest[NUMEL];
__device__ float g_fhat[NUMEL];
__device__ float g_esq[VV];
__device__ unsigned long long g_packed[VV]; // (ordered_score<<32)|idx
__device__ float g_h[NUMEL];
__device__ float g_loss;
// fp16 split operands for argmin, K=384:
//   emb:  [hi|hi|lo]   rest: [hi|lo|hi]   -> dot = hi*hi + lo*hi + hi*lo
__device__ __align__(16) __half g_embP[(size_t)VV * 384];
__device__ __align__(16) __half g_restP[(size_t)VV * 384];
// conv operands:
//  hT[b][sp=y*16+x][plane]: plane<128 = hi(h[ci]), 128..255 = lo(h[ci])
__device__ __align__(16) __half g_hT[(size_t)BB * 256 * 256];
//  wP[phi][tap][cout][384]: [hi|hi|lo]
__device__ __align__(16) __half g_wP[(size_t)4 * 9 * 128 * 384];

__device__ __forceinline__ uint32_t smem_to_u32(const void* p) {
    uint32_t a;
    asm("{ .reg .u64 t; cvta.to.shared.u64 t, %1; cvt.u32.u64 %0, t; }" : "=r"(a) : "l"(p));
    return a;
}
__device__ __forceinline__ void ldsm_x4(uint32_t& r0, uint32_t& r1, uint32_t& r2, uint32_t& r3,
                                        uint32_t addr) {
    asm volatile("ldmatrix.sync.aligned.m8n8.x4.shared.b16 {%0,%1,%2,%3}, [%4];"
                 : "=r"(r0), "=r"(r1), "=r"(r2), "=r"(r3) : "r"(addr));
}
__device__ __forceinline__ void mma16816(float* d, const uint32_t* a, const uint32_t* b) {
    asm volatile("mma.sync.aligned.m16n8k16.row.col.f32.f16.f16.f32 "
                 "{%0,%1,%2,%3}, {%4,%5,%6,%7}, {%8,%9}, {%0,%1,%2,%3};"
                 : "+f"(d[0]), "+f"(d[1]), "+f"(d[2]), "+f"(d[3])
                 : "r"(a[0]), "r"(a[1]), "r"(a[2]), "r"(a[3]), "r"(b[0]), "r"(b[1]));
}

// ---------------- init ----------------
__global__ void k_init(const float* __restrict__ f) {
    int i = blockIdx.x * 256 + threadIdx.x;
    g_frest[i] = f[i];
    g_fhat[i] = 0.f;
    if (i == 0) g_loss = 0.f;
}

// ---------------- prep emb: esq + fp16 split [hi|hi|lo] ----------------
__global__ void k_prep_emb(const float* __restrict__ emb) {
    int code = blockIdx.x * 8 + (threadIdx.x >> 5);
    int lane = threadIdx.x & 31;
    float4 v = *(const float4*)(emb + (size_t)code * CC + lane * 4);
    float s = v.x*v.x + v.y*v.y + v.z*v.z + v.w*v.w;
    #pragma unroll
    for (int o = 16; o; o >>= 1) s += __shfl_xor_sync(0xffffffffu, s, o);
    if (lane == 0) g_esq[code] = s;

    __half h0 = __float2half(v.x), h1 = __float2half(v.y);
    __half h2 = __float2half(v.z), h3 = __float2half(v.w);
    __half l0 = __float2half(v.x - __half2float(h0));
    __half l1 = __float2half(v.y - __half2float(h1));
    __half l2 = __float2half(v.z - __half2float(h2));
    __half l3 = __float2half(v.w - __half2float(h3));
    __half2 hA = __halves2half2(h0, h1), hB = __halves2half2(h2, h3);
    __half2 lA = __halves2half2(l0, l1), lB = __halves2half2(l2, l3);
    __half2* base = (__half2*)(g_embP + (size_t)code * 384);
    int c2 = lane * 2;
    base[c2] = hA; base[c2 + 1] = hB;
    base[64 + c2] = hA; base[64 + c2 + 1] = hB;
    base[128 + c2] = lA; base[128 + c2 + 1] = lB;
}

// ---------------- prep weights: wP[phi][tap][cout][384] fp16 [hi|hi|lo] ----------------
__global__ void k_prep_w(const float* __restrict__ phi_w) {
    int id = blockIdx.x;            // 4*9*128
    int cout = id & 127;
    int tap = (id >> 7) % 9;
    int phi = id / (9 * 128);
    int ci = threadIdx.x;
    float w = phi_w[(((size_t)phi * 128 + cout) * 128 + ci) * 9 + tap];
    __half hi = __float2half(w);
    __half lo = __float2half(w - __half2float(hi));
    __half* dst = g_wP + (((size_t)phi * 9 + tap) * 128 + cout) * 384;
    dst[ci] = hi; dst[128 + ci] = hi; dst[256 + ci] = lo;
}

// ---------------- pool (warp-per-output, for s>=8) ----------------
__global__ void k_pool_warp(int pn, int s, int ls, float inv) {
    int w = (blockIdx.x * 256 + threadIdx.x) >> 5;  // w = n*128 + c
    int lane = threadIdx.x & 31;
    int n = w >> 7, c = w & 127;
    int pp = pn * pn;
    int b = n / pp;
    int rem = n - b * pp;
    int py = rem / pn, px = rem - py * pn;
    const float* base = g_frest + ((size_t)(b * CC + c)) * 256 + (py * s) * 16 + px * s;
    int s2 = s * s;
    float sum = 0.f;
    for (int e = lane; e < s2; e += 32)
        sum += base[(e >> ls) * 16 + (e & (s - 1))];
    #pragma unroll
    for (int o = 16; o; o >>= 1) sum += __shfl_xor_sync(0xffffffffu, sum, o);
    if (lane == 0) {
        float m = sum * inv;
        __half hi = __float2half(m);
        __half lo = __float2half(m - __half2float(hi));
        __half* dst = g_restP + (size_t)n * 384;
        dst[c] = hi; dst[128 + c] = lo; dst[256 + c] = hi;
        if (c == 0) g_packed[n] = ~0ull;
    }
}

// ---------------- pool (thread-per-output, for s<=4) ----------------
__global__ void k_pool(int pn, int s, int N) {
    int n = blockIdx.x;
    int c = threadIdx.x;
    int b = n / (pn * pn);
    int rem = n - b * pn * pn;
    int py = rem / pn, px = rem - py * pn;
    const float* base = g_frest + ((size_t)(b * CC + c)) * 256;
    float sum = 0.f;
    for (int dy = 0; dy < s; dy++)
        for (int dx = 0; dx < s; dx++)
            sum += base[(py * s + dy) * 16 + (px * s + dx)];
    float m = sum * (1.f / (float)(s * s));
    __half hi = __float2half(m);
    __half lo = __float2half(m - __half2float(hi));
    __half* dst = g_restP + (size_t)n * 384;
    dst[c] = hi; dst[128 + c] = lo; dst[256 + c] = hi;
    if (c == 0) g_packed[n] = ~0ull;
}

// ---------------- argmin via ldmatrix + mma.sync (HMMA) ----------------
#define SM_ESQ 0
#define SM_A 512
#define SM_B (512 + 24*4096)
#define SM_TOTAL (512 + 48*4096)

__global__ __launch_bounds__(256, 1)
void k_argmin_mma(int N, int codesPerBlock) {
    extern __shared__ char smem[];
    uint32_t sb = smem_to_u32(smem);
    float* sEsq = (float*)(smem + SM_ESQ);
    int tid = threadIdx.x;
    int lane = tid & 31, wid = tid >> 5;
    int warp_m = wid >> 2;
    int warp_n = wid & 3;
    int n0 = blockIdx.x * 128;
    int v0 = blockIdx.y * codesPerBlock;
    int nTiles = codesPerBlock >> 7;

    for (int i = tid; i < 6144; i += 256) {
        int chunk = i >> 8, rr = (i >> 1) & 127, half = i & 1;
        uint4 v = make_uint4(0, 0, 0, 0);
        int n = n0 + rr;
        if (n < N)
            v = *(const uint4*)((const char*)g_restP + (size_t)n * 768 + chunk * 32 + half * 16);
        uint32_t off = (uint32_t)(chunk * 4096) +
                       (((uint32_t)(rr * 32 + half * 16)) ^ ((uint32_t)(rr & 7) << 4));
        *(uint4*)(smem + SM_A + off) = v;
    }

    const float INF = __int_as_float(0x7f800000);
    float best[8];
    int bidx[8];
    #pragma unroll
    for (int i = 0; i < 8; i++) { best[i] = INF; bidx[i] = 0; }

    uint32_t aoff[4], boff[2];
    #pragma unroll
    for (int mf = 0; mf < 4; mf++) {
        int r = warp_m * 64 + mf * 16 + (lane & 15);
        uint32_t off = (uint32_t)(r * 32 + (lane >> 4) * 16);
        aoff[mf] = sb + SM_A + (off ^ ((uint32_t)(r & 7) << 4));
    }
    #pragma unroll
    for (int nf2 = 0; nf2 < 2; nf2++) {
        int n = warp_n * 32 + nf2 * 16 + ((lane >> 4) << 3) + (lane & 7);
        uint32_t off = (uint32_t)(n * 32 + ((lane >> 3) & 1) * 16);
        boff[nf2] = sb + SM_B + (off ^ ((uint32_t)(n & 7) << 4));
    }

    for (int tt = 0; tt < nTiles; tt++) {
        int c0 = v0 + (tt << 7);
        __syncthreads();
        for (int i = tid; i < 6144; i += 256) {
            int chunk = i >> 8, rr = (i >> 1) & 127, half = i & 1;
            uint4 v = *(const uint4*)((const char*)g_embP + (size_t)(c0 + rr) * 768 + chunk * 32 + half * 16);
            uint32_t off = (uint32_t)(chunk * 4096) +
                           (((uint32_t)(rr * 32 + half * 16)) ^ ((uint32_t)(rr & 7) << 4));
            *(uint4*)(smem + SM_B + off) = v;
        }
        if (tid < 128) sEsq[tid] = g_esq[c0 + tid];
        __syncthreads();

        float acc[4][4][4];
        #pragma unroll
        for (int mf = 0; mf < 4; mf++)
            #pragma unroll
            for (int nf = 0; nf < 4; nf++)
                #pragma unroll
                for (int q = 0; q < 4; q++) acc[mf][nf][q] = 0.f;

        #pragma unroll
        for (int kc = 0; kc < 24; kc++) {
            uint32_t cb = (uint32_t)(kc * 4096);
            uint32_t a[4][4], b[4][2];
            #pragma unroll
            for (int mf = 0; mf < 4; mf++)
                ldsm_x4(a[mf][0], a[mf][1], a[mf][2], a[mf][3], aoff[mf] + cb);
            #pragma unroll
            for (int nf2 = 0; nf2 < 2; nf2++) {
                uint32_t r0, r1, r2, r3;
                ldsm_x4(r0, r1, r2, r3, boff[nf2] + cb);
                b[nf2*2][0] = r0; b[nf2*2][1] = r1;
                b[nf2*2+1][0] = r2; b[nf2*2+1][1] = r3;
            }
            #pragma unroll
            for (int mf = 0; mf < 4; mf++)
                #pragma unroll
                for (int nf = 0; nf < 4; nf++)
                    mma16816(acc[mf][nf], a[mf], b[nf]);
        }

        #pragma unroll
        for (int nf = 0; nf < 4; nf++) {
            int colL = warp_n * 32 + nf * 8 + 2 * (lane & 3);
            float es0 = sEsq[colL], es1 = sEsq[colL + 1];
            int cg = c0 + colL;
            #pragma unroll
            for (int mf = 0; mf < 4; mf++) {
                float* d = acc[mf][nf];
                int s0 = mf * 2, s1 = mf * 2 + 1;
                float v;
                v = fmaf(-2.f, d[0], es0); if (v < best[s0]) { best[s0] = v; bidx[s0] = cg; }
                v = fmaf(-2.f, d[1], es1); if (v < best[s0]) { best[s0] = v; bidx[s0] = cg + 1; }
                v = fmaf(-2.f, d[2], es0); if (v < best[s1]) { best[s1] = v; bidx[s1] = cg; }
                v = fmaf(-2.f, d[3], es1); if (v < best[s1]) { best[s1] = v; bidx[s1] = cg + 1; }
            }
        }
    }

    #pragma unroll
    for (int o = 1; o <= 2; o <<= 1) {
        #pragma unroll
        for (int s = 0; s < 8; s++) {
            float so = __shfl_xor_sync(0xffffffffu, best[s], o);
            int io = __shfl_xor_sync(0xffffffffu, bidx[s], o);
            if (so < best[s] || (so == best[s] && io < bidx[s])) { best[s] = so; bidx[s] = io; }
        }
    }
    if ((lane & 3) == 0) {
        #pragma unroll
        for (int s = 0; s < 8; s++) {
            int mf = s >> 1, h = s & 1;
            int r = n0 + warp_m * 64 + mf * 16 + (lane >> 2) + h * 8;
            if (r < N) {
                unsigned u = __float_as_uint(best[s]);
                u = (u & 0x80000000u) ? ~u : (u | 0x80000000u);
                unsigned long long p = ((unsigned long long)u << 32) | (unsigned)bidx[s];
                atomicMin(&g_packed[r], p);
            }
        }
    }
}

// ---------------- bicubic weights ----------------
template <int PN>
__device__ __forceinline__ void cubic_weights(int j, float* w) {
    float sf = (j + 0.5f) * ((float)PN / 16.f) - 0.5f;
    float tot = 0.f;
    #pragma unroll
    for (int i = 0; i < PN; i++) {
        float x = fabsf(sf - (float)i);
        float v = 0.f;
        if (x <= 1.f)      v = ((1.5f * x - 2.5f) * x) * x + 1.f;
        else if (x < 2.f)  v = ((-0.5f * x + 2.5f) * x - 4.f) * x + 2.f;
        w[i] = v;
        tot += v;
    }
    float r = 1.f / tot;
    #pragma unroll
    for (int i = 0; i < PN; i++) w[i] *= r;
}

// ---------------- gather + bicubic upsample (also writes hT fp16 split) ----------------
// grid (32 b, 4 quarter) for parallelism
template <int PN>
__global__ void k_upsample(const float* __restrict__ emb) {
    const int NP = PN * PN;
    __shared__ float g[64][128];
    __shared__ float wtab[16][8];
    int b = blockIdx.x;
    for (int i = threadIdx.x; i < NP * CC; i += 256) {
        int p = i >> 7, c = i & 127;
        unsigned idx = (unsigned)(g_packed[b * NP + p] & 0xffffffffu);
        g[p][c] = emb[(size_t)idx * CC + c];
    }
    if (threadIdx.x < 16) cubic_weights<PN>(threadIdx.x, &wtab[threadIdx.x][0]);
    __syncthreads();
    int o0 = blockIdx.y * 8192;
    for (int o = o0 + threadIdx.x; o < o0 + 8192; o += 256) {
        int c = o & 127;
        int sp = o >> 7;
        int x = sp & 15, y = sp >> 4;
        float acc = 0.f;
        #pragma unroll
        for (int iy = 0; iy < PN; iy++) {
            float ra = 0.f;
            #pragma unroll
            for (int ix = 0; ix < PN; ix++)
                ra += wtab[x][ix] * g[iy * PN + ix][c];
            acc += wtab[y][iy] * ra;
        }
        g_h[((size_t)(b * CC + c)) * 256 + y * 16 + x] = acc;
        __half hi = __float2half(acc);
        __half lo = __float2half(acc - __half2float(hi));
        __half* ht = g_hT + ((size_t)b * 256 + sp) * 256;
        ht[c] = hi; ht[128 + c] = lo;
    }
}

__global__ void k_gather16(const float* __restrict__ emb) {
    int n = blockIdx.x;
    int c = threadIdx.x;
    unsigned idx = (unsigned)(g_packed[n] & 0xffffffffu);
    int b = n >> 8, y = (n >> 4) & 15, x = n & 15;
    float v = emb[(size_t)idx * CC + c];
    g_h[((size_t)(b * CC + c)) * 256 + y * 16 + x] = v;
    __half hi = __float2half(v);
    __half lo = __float2half(v - __half2float(hi));
    __half* ht = g_hT + ((size_t)b * 256 + (n & 255)) * 256;
    ht[c] = hi; ht[128 + c] = lo;
}

// ---------------- Phi conv via HMMA + fused residual update / loss / output ----------------
// grid (4 mq, 32 b, 2 cout-half), 256 threads. Block: 64 spatial x 64 couts.
// smem: sIn[108 halo rows][64 planes] (13824B) + sW[9 taps][64 cout][64] (73728B)
#define SM_IN 0
#define SM_W 13824
#define SM_CONV (13824 + 73728)

__global__ __launch_bounds__(256, 2)
void k_conv_mma(int phi, const float* __restrict__ bias,
                const float* __restrict__ f, float* __restrict__ dout, int is_last) {
    extern __shared__ char smem[];
    uint32_t sb = smem_to_u32(smem);
    int tid = threadIdx.x;
    int lane = tid & 31, wid = tid >> 5;
    int mq = blockIdx.x;
    int b = blockIdx.y;
    int zc = blockIdx.z;
    int warp_m = wid >> 2, warp_n = wid & 3;

    const __half* wSrc = g_wP + (size_t)phi * 9 * 128 * 384;
    const __half* hTb = g_hT + (size_t)b * 256 * 256;

    float acc[2][2][4];
    #pragma unroll
    for (int mf = 0; mf < 2; mf++)
        #pragma unroll
        for (int nf = 0; nf < 2; nf++)
            #pragma unroll
            for (int q = 0; q < 4; q++) acc[mf][nf][q] = 0.f;

    int r0[2];
    #pragma unroll
    for (int mf = 0; mf < 2; mf++) {
        int mloc = warp_m * 32 + mf * 16 + (lane & 15);
        r0[mf] = (mloc >> 4) * 18 + (mloc & 15);
    }
    int acol = (lane >> 4) * 16;
    int nrow = warp_n * 16 + ((lane >> 4) << 3) + (lane & 7);
    int bcol = ((lane >> 3) & 1) * 16;

    const int dts[9] = {0, 1, 2, 18, 19, 20, 36, 37, 38};

    for (int kc = 0; kc < 6; kc++) {
        int srcPlane = (kc < 4 ? kc : kc - 4) * 64;
        __syncthreads();
        // stage input halo chunk: 108 rows x 64 planes
        for (int i = tid; i < 864; i += 256) {
            int lr = i >> 3, c16 = i & 7;
            int ly = lr / 18, lx = lr - ly * 18;
            int iy = mq * 4 + ly - 1, ix = lx - 1;
            uint4 v = make_uint4(0, 0, 0, 0);
            if ((unsigned)iy < 16u && (unsigned)ix < 16u)
                v = *(const uint4*)(hTb + ((size_t)(iy * 16 + ix)) * 256 + srcPlane + c16 * 8);
            *(uint4*)(smem + SM_IN + lr * 128 + ((c16 * 16) ^ ((lr & 7) << 4))) = v;
        }
        // stage 9 taps x 64 couts weight chunk
        for (int i = tid; i < 4608; i += 256) {
            int tap = i >> 9, r = (i >> 3) & 63, c16 = i & 7;
            uint4 v = *(const uint4*)(wSrc + ((size_t)tap * 128 + zc * 64 + r) * 384 + kc * 64 + c16 * 8);
            *(uint4*)(smem + SM_W + tap * 8192 + r * 128 + ((c16 * 16) ^ ((r & 7) << 4))) = v;
        }
        __syncthreads();

        for (int tap = 0; tap < 9; tap++) {
            int dt = dts[tap];
            uint32_t wbase = sb + SM_W + tap * 8192;
            #pragma unroll
            for (int kb = 0; kb < 4; kb++) {
                uint32_t a[2][4], bf[2][2];
                #pragma unroll
                for (int mf = 0; mf < 2; mf++) {
                    int rA = r0[mf] + dt;
                    uint32_t addr = sb + SM_IN + rA * 128 +
                                    (((uint32_t)(kb * 32 + acol)) ^ ((uint32_t)(rA & 7) << 4));
                    ldsm_x4(a[mf][0], a[mf][1], a[mf][2], a[mf][3], addr);
                }
                {
                    uint32_t addr = wbase + nrow * 128 +
                                    (((uint32_t)(kb * 32 + bcol)) ^ ((uint32_t)(nrow & 7) << 4));
                    uint32_t q0, q1, q2, q3;
                    ldsm_x4(q0, q1, q2, q3, addr);
                    bf[0][0] = q0; bf[0][1] = q1;
                    bf[1][0] = q2; bf[1][1] = q3;
                }
                #pragma unroll
                for (int mf = 0; mf < 2; mf++)
                    #pragma unroll
                    for (int nf = 0; nf < 2; nf++)
                        mma16816(acc[mf][nf], a[mf], bf[nf]);
            }
        }
    }

    // fused epilogue: h2 = 0.5*(h + conv + bias); fhat += h2; frest -= h2;
    // d = fhat - f; SSE; last stage writes straight-through output.
    float sse = 0.f;
    #pragma unroll
    for (int nf = 0; nf < 2; nf++) {
        int c = zc * 64 + warp_n * 16 + nf * 8 + (lane & 3) * 2;
        float bv0 = __ldg(&bias[c]), bv1 = __ldg(&bias[c + 1]);
        #pragma unroll
        for (int mf = 0; mf < 2; mf++) {
            #pragma unroll
            for (int h = 0; h < 2; h++) {
                int m = warp_m * 32 + mf * 16 + (lane >> 2) + h * 8;
                int sp = mq * 64 + m;
                size_t i0 = ((size_t)(b * CC + c)) * 256 + sp;
                size_t i1 = i0 + 256;
                float h20 = 0.5f * (g_h[i0] + acc[mf][nf][h * 2] + bv0);
                float h21 = 0.5f * (g_h[i1] + acc[mf][nf][h * 2 + 1] + bv1);
                float fh0 = g_fhat[i0] + h20;
                float fh1 = g_fhat[i1] + h21;
                g_fhat[i0] = fh0; g_fhat[i1] = fh1;
                g_frest[i0] -= h20; g_frest[i1] -= h21;
                float fv0 = f[i0], fv1 = f[i1];
                float d0 = fh0 - fv0, d1 = fh1 - fv1;
                if (is_last) { dout[i0] = d0 + fv0; dout[i1] = d1 + fv1; }
                sse += d0 * d0 + d1 * d1;
            }
        }
    }
    #pragma unroll
    for (int o = 16; o; o >>= 1) sse += __shfl_xor_sync(0xffffffffu, sse, o);
    __shared__ float ws[8];
    if (lane == 0) ws[wid] = sse;
    __syncthreads();
    if (tid == 0) {
        float t = 0.f;
        #pragma unroll
        for (int k = 0; k < 8; k++) t += ws[k];
        atomicAdd(&g_loss, t);
    }
}

__global__ void k_final(float* dout, int out_size) {
    dout[out_size - 1] = g_loss * (1.25f / (5.f * (float)NUMEL));
}

// ---------------- host ----------------
extern "C" void kernel_launch(void* const* d_in, const int* in_sizes, int n_in,
                              void* d_out, int out_size) {
    const float* f     = (const float*)d_in[0];
    const float* emb   = (const float*)d_in[1];
    const float* phi_w = (const float*)d_in[2];
    const float* phi_b = (const float*)d_in[3];
    float* out = (float*)d_out;

    cudaFuncSetAttribute(k_argmin_mma, cudaFuncAttributeMaxDynamicSharedMemorySize, SM_TOTAL);
    cudaFuncSetAttribute(k_conv_mma, cudaFuncAttributeMaxDynamicSharedMemorySize, SM_CONV);

    // Replicate np.linspace(1/12, 11/12, 4) + argmin(|ticks - si/4|) in double.
    double start = 1.0 / 12.0;
    double stop = 1.0 - 1.0 / 12.0;
    double step = (stop - start) / 3.0;
    double ticks[4];
    ticks[0] = 0.0 * step + start;
    ticks[1] = 1.0 * step + start;
    ticks[2] = 2.0 * step + start;
    ticks[3] = stop;
    int kphi[5];
    for (int si = 0; si < 5; si++) {
        double t = (double)si / 4.0;
        int bi = 0;
        double bd = fabs(ticks[0] - t);
        for (int k = 1; k < 4; k++) {
            double d = fabs(ticks[k] - t);
            if (d < bd) { bd = d; bi = k; }
        }
        kphi[si] = bi;
    }

    const int pns[5]    = {1, 2, 4, 8, 16};
    const int vsplit[5] = {64, 64, 32, 16, 4};

    k_prep_emb<<<VV / 8, 256>>>(emb);
    k_prep_w<<<4 * 9 * 128, 128>>>(phi_w);
    k_init<<<NUMEL / 256, 256>>>(f);

    for (int si = 0; si < 5; si++) {
        int pn = pns[si];
        int s = 16 / pn;
        int N = BB * pn * pn;

        if (s >= 8) {
            int ls = (s == 16) ? 4 : 3;
            k_pool_warp<<<(N * 128) / 8, 256>>>(pn, s, ls, 1.f / (float)(s * s));
        } else {
            k_pool<<<N, 128>>>(pn, s, N);
        }

        int rb = (N + 127) / 128;
        dim3 grd(rb, vsplit[si]);
        k_argmin_mma<<<grd, 256, SM_TOTAL>>>(N, VV / vsplit[si]);

        if (si < 4) {
            dim3 ug(32, 4);
            switch (pn) {
                case 1: k_upsample<1><<<ug, 256>>>(emb); break;
                case 2: k_upsample<2><<<ug, 256>>>(emb); break;
                case 4: k_upsample<4><<<ug, 256>>>(emb); break;
                case 8: k_upsample<8><<<ug, 256>>>(emb); break;
            }
        } else {
            k_gather16<<<VV, 128>>>(emb);
        }

        k_conv_mma<<<dim3(4, 32, 2), 256, SM_CONV>>>(kphi[si], phi_b + kphi[si] * 128,
                                                     f, out, si == 4 ? 1 : 0);
    }

    k_final<<<1, 1>>>(out, out_size);
}

// round 11
// speedup vs baseline: 5.7373x; 1.1970x over previous
#include <cuda_runtime.h>
#include <cuda_fp16.h>
#include <cstdint>
#include <math.h>

// Problem constants
#define BB 32
#define CC 128
#define VV 8192
#define NUMEL (BB*CC*16*16)   // 1048576

// ---------------- device scratch (no allocs allowed) ----------------
__device__ float g_frest[NUMEL];
__device__ float g_fhat[NUMEL];
__device__ float g_esq[VV];
__device__ unsigned long long g_packed[VV]; // (ordered_score<<32)|idx
__device__ float g_h[NUMEL];
__device__ float g_loss;
// fp16 split operands for argmin, K=384:
//   emb:  [hi|hi|lo]   rest: [hi|lo|hi]   -> dot = hi*hi + lo*hi + hi*lo
__device__ __align__(16) __half g_embP[(size_t)VV * 384];
__device__ __align__(16) __half g_restP[(size_t)VV * 384];
// conv operands:
//  hT[b][sp=y*16+x][plane]: plane<128 = hi(h[ci]), 128..255 = lo(h[ci])
__device__ __align__(16) __half g_hT[(size_t)BB * 256 * 256];
//  wP[phi][tap][cout][384]: [hi|hi|lo]
__device__ __align__(16) __half g_wP[(size_t)4 * 9 * 128 * 384];

__device__ __forceinline__ uint32_t smem_to_u32(const void* p) {
    uint32_t a;
    asm("{ .reg .u64 t; cvta.to.shared.u64 t, %1; cvt.u32.u64 %0, t; }" : "=r"(a) : "l"(p));
    return a;
}
__device__ __forceinline__ void ldsm_x4(uint32_t& r0, uint32_t& r1, uint32_t& r2, uint32_t& r3,
                                        uint32_t addr) {
    asm volatile("ldmatrix.sync.aligned.m8n8.x4.shared.b16 {%0,%1,%2,%3}, [%4];"
                 : "=r"(r0), "=r"(r1), "=r"(r2), "=r"(r3) : "r"(addr));
}
__device__ __forceinline__ void mma16816(float* d, const uint32_t* a, const uint32_t* b) {
    asm volatile("mma.sync.aligned.m16n8k16.row.col.f32.f16.f16.f32 "
                 "{%0,%1,%2,%3}, {%4,%5,%6,%7}, {%8,%9}, {%0,%1,%2,%3};"
                 : "+f"(d[0]), "+f"(d[1]), "+f"(d[2]), "+f"(d[3])
                 : "r"(a[0]), "r"(a[1]), "r"(a[2]), "r"(a[3]), "r"(b[0]), "r"(b[1]));
}
#define CP_ASYNC16(dst, src) \
    asm volatile("cp.async.cg.shared.global [%0], [%1], 16;" :: "r"(dst), "l"(src))
#define CP_ASYNC16_P(dst, src, sz) \
    asm volatile("cp.async.cg.shared.global [%0], [%1], 16, %2;" :: "r"(dst), "l"(src), "r"(sz))
#define CP_COMMIT() asm volatile("cp.async.commit_group;" ::: "memory")
#define CP_WAIT1()  asm volatile("cp.async.wait_group 1;" ::: "memory")
#define CP_WAIT0()  asm volatile("cp.async.wait_group 0;" ::: "memory")

// ---------------- init ----------------
__global__ void k_init(const float* __restrict__ f) {
    int i = blockIdx.x * 256 + threadIdx.x;
    g_frest[i] = f[i];
    g_fhat[i] = 0.f;
    if (i == 0) g_loss = 0.f;
}

// ---------------- prep emb: esq + fp16 split [hi|hi|lo] ----------------
__global__ void k_prep_emb(const float* __restrict__ emb) {
    int code = blockIdx.x * 8 + (threadIdx.x >> 5);
    int lane = threadIdx.x & 31;
    float4 v = *(const float4*)(emb + (size_t)code * CC + lane * 4);
    float s = v.x*v.x + v.y*v.y + v.z*v.z + v.w*v.w;
    #pragma unroll
    for (int o = 16; o; o >>= 1) s += __shfl_xor_sync(0xffffffffu, s, o);
    if (lane == 0) g_esq[code] = s;

    __half h0 = __float2half(v.x), h1 = __float2half(v.y);
    __half h2 = __float2half(v.z), h3 = __float2half(v.w);
    __half l0 = __float2half(v.x - __half2float(h0));
    __half l1 = __float2half(v.y - __half2float(h1));
    __half l2 = __float2half(v.z - __half2float(h2));
    __half l3 = __float2half(v.w - __half2float(h3));
    __half2 hA = __halves2half2(h0, h1), hB = __halves2half2(h2, h3);
    __half2 lA = __halves2half2(l0, l1), lB = __halves2half2(l2, l3);
    __half2* base = (__half2*)(g_embP + (size_t)code * 384);
    int c2 = lane * 2;
    base[c2] = hA; base[c2 + 1] = hB;
    base[64 + c2] = hA; base[64 + c2 + 1] = hB;
    base[128 + c2] = lA; base[128 + c2 + 1] = lB;
}

// ---------------- prep weights: wP[phi][tap][cout][384] fp16 [hi|hi|lo] ----------------
__global__ void k_prep_w(const float* __restrict__ phi_w) {
    int id = blockIdx.x;            // 4*9*128
    int cout = id & 127;
    int tap = (id >> 7) % 9;
    int phi = id / (9 * 128);
    int ci = threadIdx.x;
    float w = phi_w[(((size_t)phi * 128 + cout) * 128 + ci) * 9 + tap];
    __half hi = __float2half(w);
    __half lo = __float2half(w - __half2float(hi));
    __half* dst = g_wP + (((size_t)phi * 9 + tap) * 128 + cout) * 384;
    dst[ci] = hi; dst[128 + ci] = hi; dst[256 + ci] = lo;
}

// ---------------- pool (warp-per-output, for s>=8) ----------------
__global__ void k_pool_warp(int pn, int s, int ls, float inv) {
    int w = (blockIdx.x * 256 + threadIdx.x) >> 5;  // w = n*128 + c
    int lane = threadIdx.x & 31;
    int n = w >> 7, c = w & 127;
    int pp = pn * pn;
    int b = n / pp;
    int rem = n - b * pp;
    int py = rem / pn, px = rem - py * pn;
    const float* base = g_frest + ((size_t)(b * CC + c)) * 256 + (py * s) * 16 + px * s;
    int s2 = s * s;
    float sum = 0.f;
    for (int e = lane; e < s2; e += 32)
        sum += base[(e >> ls) * 16 + (e & (s - 1))];
    #pragma unroll
    for (int o = 16; o; o >>= 1) sum += __shfl_xor_sync(0xffffffffu, sum, o);
    if (lane == 0) {
        float m = sum * inv;
        __half hi = __float2half(m);
        __half lo = __float2half(m - __half2float(hi));
        __half* dst = g_restP + (size_t)n * 384;
        dst[c] = hi; dst[128 + c] = lo; dst[256 + c] = hi;
        if (c == 0) g_packed[n] = ~0ull;
    }
}

// ---------------- pool (thread-per-output, for s<=4) ----------------
__global__ void k_pool(int pn, int s, int N) {
    int n = blockIdx.x;
    int c = threadIdx.x;
    int b = n / (pn * pn);
    int rem = n - b * pn * pn;
    int py = rem / pn, px = rem - py * pn;
    const float* base = g_frest + ((size_t)(b * CC + c)) * 256;
    float sum = 0.f;
    for (int dy = 0; dy < s; dy++)
        for (int dx = 0; dx < s; dx++)
            sum += base[(py * s + dy) * 16 + (px * s + dx)];
    float m = sum * (1.f / (float)(s * s));
    __half hi = __float2half(m);
    __half lo = __float2half(m - __half2float(hi));
    __half* dst = g_restP + (size_t)n * 384;
    dst[c] = hi; dst[128 + c] = lo; dst[256 + c] = hi;
    if (c == 0) g_packed[n] = ~0ull;
}

// ---------------- argmin via ldmatrix + mma.sync, cp.async half-pipelined ----------------
#define SM_ESQ 0
#define SM_A 512
#define SM_B (512 + 24*4096)
#define SM_TOTAL (512 + 48*4096)

// copy one half (12 k-chunks, 48KB) of code tile starting at code c0
__device__ __forceinline__ void copyB_half(char* smem, int tid, int c0, int half) {
    #pragma unroll
    for (int j = 0; j < 12; j++) {
        int i = tid + j * 256 + half * 3072;   // uint4 index in [0,6144)
        int chunk = i >> 8, rr = (i >> 1) & 127, hh = i & 1;
        const char* src = (const char*)g_embP + (size_t)(c0 + rr) * 768 + chunk * 32 + hh * 16;
        uint32_t dst = smem_to_u32(smem) + SM_B + (uint32_t)(chunk * 4096) +
                       (((uint32_t)(rr * 32 + hh * 16)) ^ ((uint32_t)(rr & 7) << 4));
        CP_ASYNC16(dst, src);
    }
}

__global__ __launch_bounds__(256, 1)
void k_argmin_mma(int N, int codesPerBlock) {
    extern __shared__ char smem[];
    uint32_t sb = smem_to_u32(smem);
    float* sEsq = (float*)(smem + SM_ESQ);
    int tid = threadIdx.x;
    int lane = tid & 31, wid = tid >> 5;
    int warp_m = wid >> 2;
    int warp_n = wid & 3;
    int n0 = blockIdx.x * 128;
    int v0 = blockIdx.y * codesPerBlock;
    int nTiles = codesPerBlock >> 7;

    // A stage via cp.async (zero-fill rows beyond N); grouped with first B half
    #pragma unroll
    for (int j = 0; j < 24; j++) {
        int i = tid + j * 256;
        int chunk = i >> 8, rr = (i >> 1) & 127, half = i & 1;
        int n = n0 + rr;
        const char* src = (const char*)g_restP + (size_t)n * 768 + chunk * 32 + half * 16;
        uint32_t dst = sb + SM_A + (uint32_t)(chunk * 4096) +
                       (((uint32_t)(rr * 32 + half * 16)) ^ ((uint32_t)(rr & 7) << 4));
        CP_ASYNC16_P(dst, src, n < N ? 16u : 0u);
    }
    copyB_half(smem, tid, v0, 0);
    CP_COMMIT();

    const float INF = __int_as_float(0x7f800000);
    float best[8];
    int bidx[8];
    #pragma unroll
    for (int i = 0; i < 8; i++) { best[i] = INF; bidx[i] = 0; }

    uint32_t aoff[4], boff[2];
    #pragma unroll
    for (int mf = 0; mf < 4; mf++) {
        int r = warp_m * 64 + mf * 16 + (lane & 15);
        uint32_t off = (uint32_t)(r * 32 + (lane >> 4) * 16);
        aoff[mf] = sb + SM_A + (off ^ ((uint32_t)(r & 7) << 4));
    }
    #pragma unroll
    for (int nf2 = 0; nf2 < 2; nf2++) {
        int n = warp_n * 32 + nf2 * 16 + ((lane >> 4) << 3) + (lane & 7);
        uint32_t off = (uint32_t)(n * 32 + ((lane >> 3) & 1) * 16);
        boff[nf2] = sb + SM_B + (off ^ ((uint32_t)(n & 7) << 4));
    }

    for (int tt = 0; tt < nTiles; tt++) {
        int c0 = v0 + (tt << 7);
        // issue H1 of current tile (H1 buffer free: prior tile's H1 readers done at bottom sync)
        copyB_half(smem, tid, c0, 1);
        CP_COMMIT();
        CP_WAIT1();               // H0(tt) (+A on tt=0) arrived
        __syncthreads();

        if (tid < 32) {
            float4 e = *(const float4*)(g_esq + c0 + tid * 4);
            *(float4*)(sEsq + tid * 4) = e;
        }

        float acc[4][4][4];
        #pragma unroll
        for (int mf = 0; mf < 4; mf++)
            #pragma unroll
            for (int nf = 0; nf < 4; nf++)
                #pragma unroll
                for (int q = 0; q < 4; q++) acc[mf][nf][q] = 0.f;

        // compute on H0 (kc 0..11)
        #pragma unroll
        for (int kc = 0; kc < 12; kc++) {
            uint32_t cb = (uint32_t)(kc * 4096);
            uint32_t a[4][4], b[4][2];
            #pragma unroll
            for (int mf = 0; mf < 4; mf++)
                ldsm_x4(a[mf][0], a[mf][1], a[mf][2], a[mf][3], aoff[mf] + cb);
            #pragma unroll
            for (int nf2 = 0; nf2 < 2; nf2++) {
                uint32_t r0, r1, r2, r3;
                ldsm_x4(r0, r1, r2, r3, boff[nf2] + cb);
                b[nf2*2][0] = r0; b[nf2*2][1] = r1;
                b[nf2*2+1][0] = r2; b[nf2*2+1][1] = r3;
            }
            #pragma unroll
            for (int mf = 0; mf < 4; mf++)
                #pragma unroll
                for (int nf = 0; nf < 4; nf++)
                    mma16816(acc[mf][nf], a[mf], b[nf]);
        }
        __syncthreads();          // all warps done reading H0 -> safe to overwrite
        if (tt + 1 < nTiles) copyB_half(smem, tid, c0 + 128, 0);
        CP_COMMIT();
        CP_WAIT1();               // H1(tt) arrived
        __syncthreads();

        // compute on H1 (kc 12..23)
        #pragma unroll
        for (int kc = 12; kc < 24; kc++) {
            uint32_t cb = (uint32_t)(kc * 4096);
            uint32_t a[4][4], b[4][2];
            #pragma unroll
            for (int mf = 0; mf < 4; mf++)
                ldsm_x4(a[mf][0], a[mf][1], a[mf][2], a[mf][3], aoff[mf] + cb);
            #pragma unroll
            for (int nf2 = 0; nf2 < 2; nf2++) {
                uint32_t r0, r1, r2, r3;
                ldsm_x4(r0, r1, r2, r3, boff[nf2] + cb);
                b[nf2*2][0] = r0; b[nf2*2][1] = r1;
                b[nf2*2+1][0] = r2; b[nf2*2+1][1] = r3;
            }
            #pragma unroll
            for (int mf = 0; mf < 4; mf++)
                #pragma unroll
                for (int nf = 0; nf < 4; nf++)
                    mma16816(acc[mf][nf], a[mf], b[nf]);
        }

        // epilogue: score + running argmin (strict <, ascending col order)
        #pragma unroll
        for (int nf = 0; nf < 4; nf++) {
            int colL = warp_n * 32 + nf * 8 + 2 * (lane & 3);
            float es0 = sEsq[colL], es1 = sEsq[colL + 1];
            int cg = c0 + colL;
            #pragma unroll
            for (int mf = 0; mf < 4; mf++) {
                float* d = acc[mf][nf];
                int s0 = mf * 2, s1 = mf * 2 + 1;
                float v;
                v = fmaf(-2.f, d[0], es0); if (v < best[s0]) { best[s0] = v; bidx[s0] = cg; }
                v = fmaf(-2.f, d[1], es1); if (v < best[s0]) { best[s0] = v; bidx[s0] = cg + 1; }
                v = fmaf(-2.f, d[2], es0); if (v < best[s1]) { best[s1] = v; bidx[s1] = cg; }
                v = fmaf(-2.f, d[3], es1); if (v < best[s1]) { best[s1] = v; bidx[s1] = cg + 1; }
            }
        }
        __syncthreads();          // H1 + sEsq readers done before next iter's writes
    }

    #pragma unroll
    for (int o = 1; o <= 2; o <<= 1) {
        #pragma unroll
        for (int s = 0; s < 8; s++) {
            float so = __shfl_xor_sync(0xffffffffu, best[s], o);
            int io = __shfl_xor_sync(0xffffffffu, bidx[s], o);
            if (so < best[s] || (so == best[s] && io < bidx[s])) { best[s] = so; bidx[s] = io; }
        }
    }
    if ((lane & 3) == 0) {
        #pragma unroll
        for (int s = 0; s < 8; s++) {
            int mf = s >> 1, h = s & 1;
            int r = n0 + warp_m * 64 + mf * 16 + (lane >> 2) + h * 8;
            if (r < N) {
                unsigned u = __float_as_uint(best[s]);
                u = (u & 0x80000000u) ? ~u : (u | 0x80000000u);
                unsigned long long p = ((unsigned long long)u << 32) | (unsigned)bidx[s];
                atomicMin(&g_packed[r], p);
            }
        }
    }
}

// ---------------- bicubic weights ----------------
template <int PN>
__device__ __forceinline__ void cubic_weights(int j, float* w) {
    float sf = (j + 0.5f) * ((float)PN / 16.f) - 0.5f;
    float tot = 0.f;
    #pragma unroll
    for (int i = 0; i < PN; i++) {
        float x = fabsf(sf - (float)i);
        float v = 0.f;
        if (x <= 1.f)      v = ((1.5f * x - 2.5f) * x) * x + 1.f;
        else if (x < 2.f)  v = ((-0.5f * x + 2.5f) * x - 4.f) * x + 2.f;
        w[i] = v;
        tot += v;
    }
    float r = 1.f / tot;
    #pragma unroll
    for (int i = 0; i < PN; i++) w[i] *= r;
}

// ---------------- gather + bicubic upsample (also writes hT fp16 split) ----------------
template <int PN>
__global__ void k_upsample(const float* __restrict__ emb) {
    const int NP = PN * PN;
    __shared__ float g[64][128];
    __shared__ float wtab[16][8];
    int b = blockIdx.x;
    for (int i = threadIdx.x; i < NP * CC; i += 256) {
        int p = i >> 7, c = i & 127;
        unsigned idx = (unsigned)(g_packed[b * NP + p] & 0xffffffffu);
        g[p][c] = emb[(size_t)idx * CC + c];
    }
    if (threadIdx.x < 16) cubic_weights<PN>(threadIdx.x, &wtab[threadIdx.x][0]);
    __syncthreads();
    int o0 = blockIdx.y * 8192;
    for (int o = o0 + threadIdx.x; o < o0 + 8192; o += 256) {
        int c = o & 127;
        int sp = o >> 7;
        int x = sp & 15, y = sp >> 4;
        float acc = 0.f;
        #pragma unroll
        for (int iy = 0; iy < PN; iy++) {
            float ra = 0.f;
            #pragma unroll
            for (int ix = 0; ix < PN; ix++)
                ra += wtab[x][ix] * g[iy * PN + ix][c];
            acc += wtab[y][iy] * ra;
        }
        g_h[((size_t)(b * CC + c)) * 256 + y * 16 + x] = acc;
        __half hi = __float2half(acc);
        __half lo = __float2half(acc - __half2float(hi));
        __half* ht = g_hT + ((size_t)b * 256 + sp) * 256;
        ht[c] = hi; ht[128 + c] = lo;
    }
}

__global__ void k_gather16(const float* __restrict__ emb) {
    int n = blockIdx.x;
    int c = threadIdx.x;
    unsigned idx = (unsigned)(g_packed[n] & 0xffffffffu);
    int b = n >> 8, y = (n >> 4) & 15, x = n & 15;
    float v = emb[(size_t)idx * CC + c];
    g_h[((size_t)(b * CC + c)) * 256 + y * 16 + x] = v;
    __half hi = __float2half(v);
    __half lo = __float2half(v - __half2float(hi));
    __half* ht = g_hT + ((size_t)b * 256 + (n & 255)) * 256;
    ht[c] = hi; ht[128 + c] = lo;
}

// ---------------- Phi conv via HMMA + fused residual update / loss / output ----------------
#define SM_IN 0
#define SM_W 13824
#define SM_CONV (13824 + 73728)

__global__ __launch_bounds__(256, 2)
void k_conv_mma(int phi, const float* __restrict__ bias,
                const float* __restrict__ f, float* __restrict__ dout, int is_last) {
    extern __shared__ char smem[];
    uint32_t sb = smem_to_u32(smem);
    int tid = threadIdx.x;
    int lane = tid & 31, wid = tid >> 5;
    int mq = blockIdx.x;
    int b = blockIdx.y;
    int zc = blockIdx.z;
    int warp_m = wid >> 2, warp_n = wid & 3;

    const __half* wSrc = g_wP + (size_t)phi * 9 * 128 * 384;
    const __half* hTb = g_hT + (size_t)b * 256 * 256;

    float acc[2][2][4];
    #pragma unroll
    for (int mf = 0; mf < 2; mf++)
        #pragma unroll
        for (int nf = 0; nf < 2; nf++)
            #pragma unroll
            for (int q = 0; q < 4; q++) acc[mf][nf][q] = 0.f;

    int r0[2];
    #pragma unroll
    for (int mf = 0; mf < 2; mf++) {
        int mloc = warp_m * 32 + mf * 16 + (lane & 15);
        r0[mf] = (mloc >> 4) * 18 + (mloc & 15);
    }
    int acol = (lane >> 4) * 16;
    int nrow = warp_n * 16 + ((lane >> 4) << 3) + (lane & 7);
    int bcol = ((lane >> 3) & 1) * 16;

    const int dts[9] = {0, 1, 2, 18, 19, 20, 36, 37, 38};

    for (int kc = 0; kc < 6; kc++) {
        int srcPlane = (kc < 4 ? kc : kc - 4) * 64;
        __syncthreads();
        // stage input halo chunk via cp.async (zero-fill OOB): 864 uint4
        #pragma unroll
        for (int j = 0; j < 4; j++) {
            int i = tid + j * 256;
            if (i < 864) {
                int lr = i >> 3, c16 = i & 7;
                int ly = lr / 18, lx = lr - ly * 18;
                int iy = mq * 4 + ly - 1, ix = lx - 1;
                unsigned inb = ((unsigned)iy < 16u && (unsigned)ix < 16u) ? 16u : 0u;
                int spc = ((iy & 15) * 16 + (ix & 15));
                const char* src = (const char*)(hTb + (size_t)spc * 256 + srcPlane + c16 * 8);
                uint32_t dst = sb + SM_IN + (uint32_t)(lr * 128) +
                               (((uint32_t)(c16 * 16)) ^ ((uint32_t)(lr & 7) << 4));
                CP_ASYNC16_P(dst, src, inb);
            }
        }
        // stage 9 taps x 64 couts weight chunk via cp.async: 4608 uint4
        #pragma unroll
        for (int j = 0; j < 18; j++) {
            int i = tid + j * 256;
            int tap = i >> 9, r = (i >> 3) & 63, c16 = i & 7;
            const char* src = (const char*)(wSrc + ((size_t)tap * 128 + zc * 64 + r) * 384 + kc * 64 + c16 * 8);
            uint32_t dst = sb + SM_W + (uint32_t)(tap * 8192 + r * 128) +
                           (((uint32_t)(c16 * 16)) ^ ((uint32_t)(r & 7) << 4));
            CP_ASYNC16(dst, src);
        }
        CP_COMMIT();
        CP_WAIT0();
        __syncthreads();

        for (int tap = 0; tap < 9; tap++) {
            int dt = dts[tap];
            uint32_t wbase = sb + SM_W + tap * 8192;
            #pragma unroll
            for (int kb = 0; kb < 4; kb++) {
                uint32_t a[2][4], bf[2][2];
                #pragma unroll
                for (int mf = 0; mf < 2; mf++) {
                    int rA = r0[mf] + dt;
                    uint32_t addr = sb + SM_IN + rA * 128 +
                                    (((uint32_t)(kb * 32 + acol)) ^ ((uint32_t)(rA & 7) << 4));
                    ldsm_x4(a[mf][0], a[mf][1], a[mf][2], a[mf][3], addr);
                }
                {
                    uint32_t addr = wbase + nrow * 128 +
                                    (((uint32_t)(kb * 32 + bcol)) ^ ((uint32_t)(nrow & 7) << 4));
                    uint32_t q0, q1, q2, q3;
                    ldsm_x4(q0, q1, q2, q3, addr);
                    bf[0][0] = q0; bf[0][1] = q1;
                    bf[1][0] = q2; bf[1][1] = q3;
                }
                #pragma unroll
                for (int mf = 0; mf < 2; mf++)
                    #pragma unroll
                    for (int nf = 0; nf < 2; nf++)
                        mma16816(acc[mf][nf], a[mf], bf[nf]);
            }
        }
    }

    // fused epilogue: h2 = 0.5*(h + conv + bias); fhat += h2; frest -= h2;
    // d = fhat - f; SSE; last stage writes straight-through output.
    float sse = 0.f;
    #pragma unroll
    for (int nf = 0; nf < 2; nf++) {
        int c = zc * 64 + warp_n * 16 + nf * 8 + (lane & 3) * 2;
        float bv0 = __ldg(&bias[c]), bv1 = __ldg(&bias[c + 1]);
        #pragma unroll
        for (int mf = 0; mf < 2; mf++) {
            #pragma unroll
            for (int h = 0; h < 2; h++) {
                int m = warp_m * 32 + mf * 16 + (lane >> 2) + h * 8;
                int sp = mq * 64 + m;
                size_t i0 = ((size_t)(b * CC + c)) * 256 + sp;
                size_t i1 = i0 + 256;
                float h20 = 0.5f * (g_h[i0] + acc[mf][nf][h * 2] + bv0);
                float h21 = 0.5f * (g_h[i1] + acc[mf][nf][h * 2 + 1] + bv1);
                float fh0 = g_fhat[i0] + h20;
                float fh1 = g_fhat[i1] + h21;
                g_fhat[i0] = fh0; g_fhat[i1] = fh1;
                g_frest[i0] -= h20; g_frest[i1] -= h21;
                float fv0 = f[i0], fv1 = f[i1];
                float d0 = fh0 - fv0, d1 = fh1 - fv1;
                if (is_last) { dout[i0] = d0 + fv0; dout[i1] = d1 + fv1; }
                sse += d0 * d0 + d1 * d1;
            }
        }
    }
    #pragma unroll
    for (int o = 16; o; o >>= 1) sse += __shfl_xor_sync(0xffffffffu, sse, o);
    __shared__ float ws[8];
    if (lane == 0) ws[wid] = sse;
    __syncthreads();
    if (tid == 0) {
        float t = 0.f;
        #pragma unroll
        for (int k = 0; k < 8; k++) t += ws[k];
        atomicAdd(&g_loss, t);
    }
}

__global__ void k_final(float* dout, int out_size) {
    dout[out_size - 1] = g_loss * (1.25f / (5.f * (float)NUMEL));
}

// ---------------- host ----------------
extern "C" void kernel_launch(void* const* d_in, const int* in_sizes, int n_in,
                              void* d_out, int out_size) {
    const float* f     = (const float*)d_in[0];
    const float* emb   = (const float*)d_in[1];
    const float* phi_w = (const float*)d_in[2];
    const float* phi_b = (const float*)d_in[3];
    float* out = (float*)d_out;

    cudaFuncSetAttribute(k_argmin_mma, cudaFuncAttributeMaxDynamicSharedMemorySize, SM_TOTAL);
    cudaFuncSetAttribute(k_conv_mma, cudaFuncAttributeMaxDynamicSharedMemorySize, SM_CONV);

    // Replicate np.linspace(1/12, 11/12, 4) + argmin(|ticks - si/4|) in double.
    double start = 1.0 / 12.0;
    double stop = 1.0 - 1.0 / 12.0;
    double step = (stop - start) / 3.0;
    double ticks[4];
    ticks[0] = 0.0 * step + start;
    ticks[1] = 1.0 * step + start;
    ticks[2] = 2.0 * step + start;
    ticks[3] = stop;
    int kphi[5];
    for (int si = 0; si < 5; si++) {
        double t = (double)si / 4.0;
        int bi = 0;
        double bd = fabs(ticks[0] - t);
        for (int k = 1; k < 4; k++) {
            double d = fabs(ticks[k] - t);
            if (d < bd) { bd = d; bi = k; }
        }
        kphi[si] = bi;
    }

    const int pns[5]    = {1, 2, 4, 8, 16};
    const int vsplit[5] = {64, 64, 32, 8, 2};

    k_prep_emb<<<VV / 8, 256>>>(emb);
    k_prep_w<<<4 * 9 * 128, 128>>>(phi_w);
    k_init<<<NUMEL / 256, 256>>>(f);

    for (int si = 0; si < 5; si++) {
        int pn = pns[si];
        int s = 16 / pn;
        int N = BB * pn * pn;

        if (s >= 8) {
            int ls = (s == 16) ? 4 : 3;
            k_pool_warp<<<(N * 128) / 8, 256>>>(pn, s, ls, 1.f / (float)(s * s));
        } else {
            k_pool<<<N, 128>>>(pn, s, N);
        }

        int rb = (N + 127) / 128;
        dim3 grd(rb, vsplit[si]);
        k_argmin_mma<<<grd, 256, SM_TOTAL>>>(N, VV / vsplit[si]);

        if (si < 4) {
            dim3 ug(32, 4);
            switch (pn) {
                case 1: k_upsample<1><<<ug, 256>>>(emb); break;
                case 2: k_upsample<2><<<ug, 256>>>(emb); break;
                case 4: k_upsample<4><<<ug, 256>>>(emb); break;
                case 8: k_upsample<8><<<ug, 256>>>(emb); break;
            }
        } else {
            k_gather16<<<VV, 128>>>(emb);
        }

        k_conv_mma<<<dim3(4, 32, 2), 256, SM_CONV>>>(kphi[si], phi_b + kphi[si] * 128,
                                                     f, out, si == 4 ? 1 : 0);
    }

    k_final<<<1, 1>>>(out, out_size);
}